// round 6
// baseline (speedup 1.0000x reference)
#include <cuda_runtime.h>

// SR_Loss: NN(obj->sr) + ray-triangle parity interior test + reductions.
// obj 8192x3, sr 4096x3, verts 4100x3, normals 4096x3, faces 4096x3.
// Output: [pen_dist, cmap(8192)] = 8193 f32.
//
// 2 kernels: prep (face constants + sr packing + counter reset),
// main (fused NN + parity + last-block final reduction).

#define N_OBJ  8192
#define N_SR   4096
#define N_F    4096
#define NPAIR  (N_F / 2)
#define EPSF   1e-8f
#define EPSQ   1e-16f   // EPSF^2
#define NBLK   (N_OBJ / 32)

typedef unsigned long long u64;

// ---------------- scratch (device globals; no allocation allowed) ----------
__device__ float4 g_sr4[N_SR];          // sr point + |s|^2
__device__ float4 g_face4[NPAIR * 8];   // pair-interleaved face constants (32 f/pair)
__device__ float  g_part[NBLK];         // per-block pen partial sums
__device__ unsigned int g_ctr;          // arrival counter for last-block reduce

// ---------------- f32x2 packed helpers (sm_103a) ---------------------------
__device__ __forceinline__ u64 pk(float lo, float hi) {
    u64 r;
    asm("mov.b64 %0, {%1, %2};" : "=l"(r)
        : "r"(__float_as_uint(lo)), "r"(__float_as_uint(hi)));
    return r;
}
__device__ __forceinline__ void upk(u64 v, float& lo, float& hi) {
    unsigned int a, b;
    asm("mov.b64 {%0, %1}, %2;" : "=r"(a), "=r"(b) : "l"(v));
    lo = __uint_as_float(a);
    hi = __uint_as_float(b);
}
__device__ __forceinline__ u64 f2mul(u64 a, u64 b) {
    u64 r;
    asm("mul.rn.f32x2 %0, %1, %2;" : "=l"(r) : "l"(a), "l"(b));
    return r;
}
__device__ __forceinline__ u64 f2fma(u64 a, u64 b, u64 c) {
    u64 r;
    asm("fma.rn.f32x2 %0, %1, %2, %3;" : "=l"(r) : "l"(a), "l"(b), "l"(c));
    return r;
}

// ---------------- prep: pack sr, precompute face constants -----------------
// Face record (16 floats): n(3), v0.n, c01(3), -v0.c01, c12(3), -v1.c12,
// c20(3), -v2.c20, c_ab = cross(n, vb - va). Pair-interleaved: for pair p,
// slot q at float index p*32 + 2*q + (f&1) -> one 16B load = two f32x2 operands.
__global__ void prep_kernel(const float* __restrict__ sr,
                            const float* __restrict__ hv,
                            const float* __restrict__ fn,
                            const int*   __restrict__ hf) {
    int f = blockIdx.x * blockDim.x + threadIdx.x;
    if (f == 0) g_ctr = 0;
    if (f >= N_F) return;

    float sx = sr[3 * f + 0], sy = sr[3 * f + 1], sz = sr[3 * f + 2];
    g_sr4[f] = make_float4(sx, sy, sz, sx * sx + sy * sy + sz * sz);

    int i0 = hf[3 * f + 0], i1 = hf[3 * f + 1], i2 = hf[3 * f + 2];
    float nx = fn[3 * f + 0], ny = fn[3 * f + 1], nz = fn[3 * f + 2];
    float v0x = hv[3 * i0 + 0], v0y = hv[3 * i0 + 1], v0z = hv[3 * i0 + 2];
    float v1x = hv[3 * i1 + 0], v1y = hv[3 * i1 + 1], v1z = hv[3 * i1 + 2];
    float v2x = hv[3 * i2 + 0], v2y = hv[3 * i2 + 1], v2z = hv[3 * i2 + 2];

    float vals[16];
    vals[0] = nx; vals[1] = ny; vals[2] = nz;
    vals[3] = v0x * nx + v0y * ny + v0z * nz;
    {
        float wx = v1x - v0x, wy = v1y - v0y, wz = v1z - v0z;
        float cx = ny * wz - nz * wy, cy = nz * wx - nx * wz, cz = nx * wy - ny * wx;
        vals[4] = cx; vals[5] = cy; vals[6] = cz;
        vals[7] = -(v0x * cx + v0y * cy + v0z * cz);
    }
    {
        float wx = v2x - v1x, wy = v2y - v1y, wz = v2z - v1z;
        float cx = ny * wz - nz * wy, cy = nz * wx - nx * wz, cz = nx * wy - ny * wx;
        vals[8] = cx; vals[9] = cy; vals[10] = cz;
        vals[11] = -(v1x * cx + v1y * cy + v1z * cz);
    }
    {
        float wx = v0x - v2x, wy = v0y - v2y, wz = v0z - v2z;
        float cx = ny * wz - nz * wy, cy = nz * wx - nx * wz, cz = nx * wy - ny * wx;
        vals[12] = cx; vals[13] = cy; vals[14] = cz;
        vals[15] = -(v2x * cx + v2y * cy + v2z * cz);
    }

    int p = f >> 1, h = f & 1;
    float* out = reinterpret_cast<float*>(g_face4) + p * 32 + h;
#pragma unroll
    for (int q = 0; q < 16; q++) out[2 * q] = vals[q];
}

// ---------------- main: fused NN + cmap + parity + full reduction ----------
__global__ void __launch_bounds__(256, 2) main_kernel(const float* __restrict__ obj,
                                                      float* __restrict__ out) {
    __shared__ float4 s_po[32];   // point o
    __shared__ float4 s_pd[32];   // D = trg - o, .w = |D|^2
    __shared__ int    s_cnt[8][32];
    __shared__ int    s_last;
    __shared__ float  s_red[256];

    int wid = threadIdx.x >> 5, lane = threadIdx.x & 31;
    int pbase = blockIdx.x * 32 + wid * 4;

    // ---- Phase A: NN for 4 points per warp ----
    float ox0 = obj[3 * (pbase + 0) + 0], oy0 = obj[3 * (pbase + 0) + 1], oz0 = obj[3 * (pbase + 0) + 2];
    float ox1 = obj[3 * (pbase + 1) + 0], oy1 = obj[3 * (pbase + 1) + 1], oz1 = obj[3 * (pbase + 1) + 2];
    float ox2 = obj[3 * (pbase + 2) + 0], oy2 = obj[3 * (pbase + 2) + 1], oz2 = obj[3 * (pbase + 2) + 2];
    float ox3 = obj[3 * (pbase + 3) + 0], oy3 = obj[3 * (pbase + 3) + 1], oz3 = obj[3 * (pbase + 3) + 2];
    float o20 = ox0 * ox0 + oy0 * oy0 + oz0 * oz0;
    float o21 = ox1 * ox1 + oy1 * oy1 + oz1 * oz1;
    float o22 = ox2 * ox2 + oy2 * oy2 + oz2 * oz2;
    float o23 = ox3 * ox3 + oy3 * oy3 + oz3 * oz3;

    float b0 = 3.402823466e38f, b1 = b0, b2 = b0, b3 = b0;
    int j0 = 0, j1 = 0, j2 = 0, j3 = 0;

#pragma unroll 4
    for (int j = lane; j < N_SR; j += 32) {
        float4 s = __ldg(&g_sr4[j]);
        float d0 = fmaf(-2.0f, ox0 * s.x + fmaf(oy0, s.y, oz0 * s.z), o20 + s.w);
        float d1 = fmaf(-2.0f, ox1 * s.x + fmaf(oy1, s.y, oz1 * s.z), o21 + s.w);
        float d2 = fmaf(-2.0f, ox2 * s.x + fmaf(oy2, s.y, oz2 * s.z), o22 + s.w);
        float d3 = fmaf(-2.0f, ox3 * s.x + fmaf(oy3, s.y, oz3 * s.z), o23 + s.w);
        if (d0 < b0) { b0 = d0; j0 = j; }
        if (d1 < b1) { b1 = d1; j1 = j; }
        if (d2 < b2) { b2 = d2; j2 = j; }
        if (d3 < b3) { b3 = d3; j3 = j; }
    }
#pragma unroll
    for (int off = 16; off; off >>= 1) {
        float t; int tj;
        t = __shfl_down_sync(~0u, b0, off); tj = __shfl_down_sync(~0u, j0, off);
        if (t < b0 || (t == b0 && tj < j0)) { b0 = t; j0 = tj; }
        t = __shfl_down_sync(~0u, b1, off); tj = __shfl_down_sync(~0u, j1, off);
        if (t < b1 || (t == b1 && tj < j1)) { b1 = t; j1 = tj; }
        t = __shfl_down_sync(~0u, b2, off); tj = __shfl_down_sync(~0u, j2, off);
        if (t < b2 || (t == b2 && tj < j2)) { b2 = t; j2 = tj; }
        t = __shfl_down_sync(~0u, b3, off); tj = __shfl_down_sync(~0u, j3, off);
        if (t < b3 || (t == b3 && tj < j3)) { b3 = t; j3 = tj; }
    }

    if (lane == 0) {
        float obx[4] = {ox0, ox1, ox2, ox3};
        float oby[4] = {oy0, oy1, oy2, oy3};
        float obz[4] = {oz0, oz1, oz2, oz3};
        float bb[4] = {b0, b1, b2, b3};
        int   jj[4] = {j0, j1, j2, j3};
#pragma unroll
        for (int k = 0; k < 4; k++) {
            float4 s = g_sr4[jj[k]];
            float Dx = s.x - obx[k], Dy = s.y - oby[k], Dz = s.z - obz[k];
            s_po[wid * 4 + k] = make_float4(obx[k], oby[k], obz[k], 0.0f);
            s_pd[wid * 4 + k] = make_float4(Dx, Dy, Dz, Dx * Dx + Dy * Dy + Dz * Dz);
            float nnd = sqrtf(fmaxf(bb[k], 0.0f));
            out[1 + pbase + k] = 2.0f / (1.0f + expf(100.0f * nnd));
        }
    }
    __syncthreads();

    // ---- Phase B: parity over faces (division-free, f32x2, 2 faces/op) ----
    // Tight register budget: persistent packed set = OX,OY,OZ,DX,DY,DZ + 3
    // constants. num = V0N - n.o via NEG1 fma (no negated-o registers).
    float4 po = s_po[lane];
    float4 pd = s_pd[lane];

    u64 OX = pk(po.x, po.x), OY = pk(po.y, po.y), OZ = pk(po.z, po.z);
    u64 DX = pk(pd.x, pd.x), DY = pk(pd.y, pd.y), DZ = pk(pd.z, pd.z);
    u64 NEG1 = pk(-1.0f, -1.0f);
    u64 MEPS = pk(-EPSF, -EPSF);
    u64 NEGQ = pk(-EPSQ, -EPSQ);

    int cnt = 0;
    const ulonglong2* __restrict__ fb =
        reinterpret_cast<const ulonglong2*>(g_face4) + (wid * (NPAIR / 8)) * 8;

    for (int q = 0; q < NPAIR / 8; q++) {
        const ulonglong2* up = fb + q * 8;
        ulonglong2 t0 = __ldg(up + 0);
        ulonglong2 t1 = __ldg(up + 1);

        // normal block
        u64 no  = f2fma(t0.x, OX, f2fma(t0.y, OY, f2mul(t1.x, OZ)));
        u64 num = f2fma(no, NEG1, t1.y);
        u64 den = f2fma(t0.x, DX, f2fma(t0.y, DY, f2mul(t1.x, DZ)));

        // edge A
        ulonglong2 t2 = __ldg(up + 2);
        ulonglong2 t3 = __ldg(up + 3);
        u64 ba = f2fma(t2.x, OX, f2fma(t2.y, OY, f2fma(t3.x, OZ, t3.y)));
        u64 da = f2fma(t2.x, DX, f2fma(t2.y, DY, f2mul(t3.x, DZ)));
        u64 ra = f2mul(f2fma(ba, den, f2mul(num, da)), den);

        // edge B
        ulonglong2 t4 = __ldg(up + 4);
        ulonglong2 t5 = __ldg(up + 5);
        u64 bb_ = f2fma(t4.x, OX, f2fma(t4.y, OY, f2fma(t5.x, OZ, t5.y)));
        u64 db  = f2fma(t4.x, DX, f2fma(t4.y, DY, f2mul(t5.x, DZ)));
        u64 rb  = f2mul(f2fma(bb_, den, f2mul(num, db)), den);

        // edge C
        ulonglong2 t6 = __ldg(up + 6);
        ulonglong2 t7 = __ldg(up + 7);
        u64 bc = f2fma(t6.x, OX, f2fma(t6.y, OY, f2fma(t7.x, OZ, t7.y)));
        u64 dc = f2fma(t6.x, DX, f2fma(t6.y, DY, f2mul(t7.x, DZ)));
        u64 rc = f2mul(f2fma(bc, den, f2mul(num, dc)), den);

        u64 wv  = f2mul(f2fma(MEPS, den, num), den);   // >0  <=> t>EPS (sign-exact)
        u64 ddq = f2fma(den, den, NEGQ);               // >0  <=> |den|>EPS

        float ra0, ra1, rb0, rb1, rc0, rc1, w0, w1, q0, q1;
        upk(ra, ra0, ra1);
        upk(rb, rb0, rb1);
        upk(rc, rc0, rc1);
        upk(wv, w0, w1);
        upk(ddq, q0, q1);

        float m0 = fminf(fminf(ra0, rb0), fminf(rc0, fminf(w0, q0)));
        float m1 = fminf(fminf(ra1, rb1), fminf(rc1, fminf(w1, q1)));
        cnt += (m0 > 0.0f) ? 1 : 0;
        cnt += (m1 > 0.0f) ? 1 : 0;
    }

    s_cnt[wid][lane] = cnt;
    __syncthreads();

    if (wid == 0) {
        int tot = 0;
#pragma unroll
        for (int k = 0; k < 8; k++) tot += s_cnt[k][lane];
        float pen = (tot & 1) ? s_pd[lane].w : 0.0f;
#pragma unroll
        for (int off = 16; off; off >>= 1)
            pen += __shfl_down_sync(~0u, pen, off);
        if (lane == 0) {
            g_part[blockIdx.x] = pen;
            __threadfence();
            unsigned int t = atomicAdd(&g_ctr, 1u);
            s_last = (t == NBLK - 1) ? 1 : 0;
        }
    }
    __syncthreads();

    // ---- last block: deterministic final reduction over 256 partials ----
    if (s_last) {
        float v;
        asm volatile("ld.global.cg.f32 %0, [%1];" : "=f"(v)
                     : "l"(&g_part[threadIdx.x]));
        s_red[threadIdx.x] = v;
        __syncthreads();
#pragma unroll
        for (int off = 128; off; off >>= 1) {
            if (threadIdx.x < off) s_red[threadIdx.x] += s_red[threadIdx.x + off];
            __syncthreads();
        }
        if (threadIdx.x == 0) out[0] = sqrtf(s_red[0] + 1e-12f);
    }
}

// ---------------- launch ---------------------------------------------------
extern "C" void kernel_launch(void* const* d_in, const int* in_sizes, int n_in,
                              void* d_out, int out_size) {
    const float* obj = (const float*)d_in[0];
    const float* sr  = (const float*)d_in[1];
    const float* hv  = (const float*)d_in[2];
    const float* fn  = (const float*)d_in[3];
    const int*   hf  = (const int*)d_in[4];
    float* out = (float*)d_out;

    prep_kernel<<<(N_F + 255) / 256, 256>>>(sr, hv, fn, hf);
    main_kernel<<<NBLK, 256>>>(obj, out);
}

// round 7
// speedup vs baseline: 1.1705x; 1.1705x over previous
#include <cuda_runtime.h>

// SR_Loss: NN(obj->sr) + ray-triangle parity interior test + reductions.
// obj 8192x3, sr 4096x3, verts 4100x3, normals 4096x3, faces 4096x3.
// Output: [pen_dist, cmap(8192)] = 8193 f32.
//
// 2 kernels: prep (face constants + sr packing + counter reset),
// main (fused NN + parity + last-block final reduction).
// Phase B reads face records from double-buffered smem tiles (cp.async),
// so the hot loop issues broadcast LDS.128 instead of broadcast LDG.128.

#define N_OBJ  8192
#define N_SR   4096
#define N_F    4096
#define NPAIR  (N_F / 2)
#define EPSF   1e-8f
#define EPSQ   1e-16f   // EPSF^2
#define NBLK   (N_OBJ / 32)

#define TILE_P     128                   // face-pairs per smem tile
#define NTILE      (NPAIR / TILE_P)      // 16
#define TILE_BYTES (TILE_P * 128)        // 16 KB
#define PAIRS_PER_WARP (TILE_P / 8)      // 16

typedef unsigned long long u64;

// ---------------- scratch (device globals; no allocation allowed) ----------
__device__ float4 g_sr4[N_SR];          // sr point + |s|^2
__device__ float4 g_face4[NPAIR * 8];   // pair-interleaved face constants (32 f/pair)
__device__ float  g_part[NBLK];         // per-block pen partial sums
__device__ unsigned int g_ctr;          // arrival counter for last-block reduce

// ---------------- f32x2 packed helpers (sm_103a) ---------------------------
__device__ __forceinline__ u64 pk(float lo, float hi) {
    u64 r;
    asm("mov.b64 %0, {%1, %2};" : "=l"(r)
        : "r"(__float_as_uint(lo)), "r"(__float_as_uint(hi)));
    return r;
}
__device__ __forceinline__ void upk(u64 v, float& lo, float& hi) {
    unsigned int a, b;
    asm("mov.b64 {%0, %1}, %2;" : "=r"(a), "=r"(b) : "l"(v));
    lo = __uint_as_float(a);
    hi = __uint_as_float(b);
}
__device__ __forceinline__ u64 f2mul(u64 a, u64 b) {
    u64 r;
    asm("mul.rn.f32x2 %0, %1, %2;" : "=l"(r) : "l"(a), "l"(b));
    return r;
}
__device__ __forceinline__ u64 f2fma(u64 a, u64 b, u64 c) {
    u64 r;
    asm("fma.rn.f32x2 %0, %1, %2, %3;" : "=l"(r) : "l"(a), "l"(b), "l"(c));
    return r;
}

// cp.async 16B chunk: gmem -> smem (L2 path, no intermediate registers)
__device__ __forceinline__ void cp16(unsigned int saddr, const void* gaddr) {
    asm volatile("cp.async.cg.shared.global [%0], [%1], 16;"
                 :: "r"(saddr), "l"(gaddr));
}
__device__ __forceinline__ unsigned int smem_u32(const void* p) {
    return (unsigned int)__cvta_generic_to_shared(p);
}

// ---------------- prep: pack sr, precompute face constants -----------------
// Face record (16 floats): n(3), v0.n, c01(3), -v0.c01, c12(3), -v1.c12,
// c20(3), -v2.c20, c_ab = cross(n, vb - va). Pair-interleaved: for pair p,
// slot q at float index p*32 + 2*q + (f&1) -> one 16B load = two f32x2 operands.
__global__ void prep_kernel(const float* __restrict__ sr,
                            const float* __restrict__ hv,
                            const float* __restrict__ fn,
                            const int*   __restrict__ hf) {
    int f = blockIdx.x * blockDim.x + threadIdx.x;
    if (f == 0) g_ctr = 0;
    if (f >= N_F) return;

    float sx = sr[3 * f + 0], sy = sr[3 * f + 1], sz = sr[3 * f + 2];
    g_sr4[f] = make_float4(sx, sy, sz, sx * sx + sy * sy + sz * sz);

    int i0 = hf[3 * f + 0], i1 = hf[3 * f + 1], i2 = hf[3 * f + 2];
    float nx = fn[3 * f + 0], ny = fn[3 * f + 1], nz = fn[3 * f + 2];
    float v0x = hv[3 * i0 + 0], v0y = hv[3 * i0 + 1], v0z = hv[3 * i0 + 2];
    float v1x = hv[3 * i1 + 0], v1y = hv[3 * i1 + 1], v1z = hv[3 * i1 + 2];
    float v2x = hv[3 * i2 + 0], v2y = hv[3 * i2 + 1], v2z = hv[3 * i2 + 2];

    float vals[16];
    vals[0] = nx; vals[1] = ny; vals[2] = nz;
    vals[3] = v0x * nx + v0y * ny + v0z * nz;
    {
        float wx = v1x - v0x, wy = v1y - v0y, wz = v1z - v0z;
        float cx = ny * wz - nz * wy, cy = nz * wx - nx * wz, cz = nx * wy - ny * wx;
        vals[4] = cx; vals[5] = cy; vals[6] = cz;
        vals[7] = -(v0x * cx + v0y * cy + v0z * cz);
    }
    {
        float wx = v2x - v1x, wy = v2y - v1y, wz = v2z - v1z;
        float cx = ny * wz - nz * wy, cy = nz * wx - nx * wz, cz = nx * wy - ny * wx;
        vals[8] = cx; vals[9] = cy; vals[10] = cz;
        vals[11] = -(v1x * cx + v1y * cy + v1z * cz);
    }
    {
        float wx = v0x - v2x, wy = v0y - v2y, wz = v0z - v2z;
        float cx = ny * wz - nz * wy, cy = nz * wx - nx * wz, cz = nx * wy - ny * wx;
        vals[12] = cx; vals[13] = cy; vals[14] = cz;
        vals[15] = -(v2x * cx + v2y * cy + v2z * cz);
    }

    int p = f >> 1, h = f & 1;
    float* out = reinterpret_cast<float*>(g_face4) + p * 32 + h;
#pragma unroll
    for (int q = 0; q < 16; q++) out[2 * q] = vals[q];
}

// ---------------- main: fused NN + cmap + parity + full reduction ----------
__global__ void __launch_bounds__(256, 3) main_kernel(const float* __restrict__ obj,
                                                      float* __restrict__ out) {
    __shared__ __align__(16) char s_face[2][TILE_BYTES];   // 32 KB double buffer
    __shared__ float4 s_po[32];   // point o
    __shared__ float4 s_pd[32];   // D = trg - o, .w = |D|^2
    __shared__ int    s_cnt[8][32];
    __shared__ int    s_last;
    __shared__ float  s_red[256];

    int tid = threadIdx.x;
    int wid = tid >> 5, lane = tid & 31;
    int pbase = blockIdx.x * 32 + wid * 4;

    // ---- Phase A: NN for 4 points per warp ----
    float ox0 = obj[3 * (pbase + 0) + 0], oy0 = obj[3 * (pbase + 0) + 1], oz0 = obj[3 * (pbase + 0) + 2];
    float ox1 = obj[3 * (pbase + 1) + 0], oy1 = obj[3 * (pbase + 1) + 1], oz1 = obj[3 * (pbase + 1) + 2];
    float ox2 = obj[3 * (pbase + 2) + 0], oy2 = obj[3 * (pbase + 2) + 1], oz2 = obj[3 * (pbase + 2) + 2];
    float ox3 = obj[3 * (pbase + 3) + 0], oy3 = obj[3 * (pbase + 3) + 1], oz3 = obj[3 * (pbase + 3) + 2];
    float o20 = ox0 * ox0 + oy0 * oy0 + oz0 * oz0;
    float o21 = ox1 * ox1 + oy1 * oy1 + oz1 * oz1;
    float o22 = ox2 * ox2 + oy2 * oy2 + oz2 * oz2;
    float o23 = ox3 * ox3 + oy3 * oy3 + oz3 * oz3;

    float b0 = 3.402823466e38f, b1 = b0, b2 = b0, b3 = b0;
    int j0 = 0, j1 = 0, j2 = 0, j3 = 0;

#pragma unroll 4
    for (int j = lane; j < N_SR; j += 32) {
        float4 s = __ldg(&g_sr4[j]);
        float d0 = fmaf(-2.0f, ox0 * s.x + fmaf(oy0, s.y, oz0 * s.z), o20 + s.w);
        float d1 = fmaf(-2.0f, ox1 * s.x + fmaf(oy1, s.y, oz1 * s.z), o21 + s.w);
        float d2 = fmaf(-2.0f, ox2 * s.x + fmaf(oy2, s.y, oz2 * s.z), o22 + s.w);
        float d3 = fmaf(-2.0f, ox3 * s.x + fmaf(oy3, s.y, oz3 * s.z), o23 + s.w);
        if (d0 < b0) { b0 = d0; j0 = j; }
        if (d1 < b1) { b1 = d1; j1 = j; }
        if (d2 < b2) { b2 = d2; j2 = j; }
        if (d3 < b3) { b3 = d3; j3 = j; }
    }
#pragma unroll
    for (int off = 16; off; off >>= 1) {
        float t; int tj;
        t = __shfl_down_sync(~0u, b0, off); tj = __shfl_down_sync(~0u, j0, off);
        if (t < b0 || (t == b0 && tj < j0)) { b0 = t; j0 = tj; }
        t = __shfl_down_sync(~0u, b1, off); tj = __shfl_down_sync(~0u, j1, off);
        if (t < b1 || (t == b1 && tj < j1)) { b1 = t; j1 = tj; }
        t = __shfl_down_sync(~0u, b2, off); tj = __shfl_down_sync(~0u, j2, off);
        if (t < b2 || (t == b2 && tj < j2)) { b2 = t; j2 = tj; }
        t = __shfl_down_sync(~0u, b3, off); tj = __shfl_down_sync(~0u, j3, off);
        if (t < b3 || (t == b3 && tj < j3)) { b3 = t; j3 = tj; }
    }

    if (lane == 0) {
        float obx[4] = {ox0, ox1, ox2, ox3};
        float oby[4] = {oy0, oy1, oy2, oy3};
        float obz[4] = {oz0, oz1, oz2, oz3};
        float bb[4] = {b0, b1, b2, b3};
        int   jj[4] = {j0, j1, j2, j3};
#pragma unroll
        for (int k = 0; k < 4; k++) {
            float4 s = g_sr4[jj[k]];
            float Dx = s.x - obx[k], Dy = s.y - oby[k], Dz = s.z - obz[k];
            s_po[wid * 4 + k] = make_float4(obx[k], oby[k], obz[k], 0.0f);
            s_pd[wid * 4 + k] = make_float4(Dx, Dy, Dz, Dx * Dx + Dy * Dy + Dz * Dz);
            float nnd = sqrtf(fmaxf(bb[k], 0.0f));
            out[1 + pbase + k] = 2.0f / (1.0f + expf(100.0f * nnd));
        }
    }

    // ---- stage tile 0 while phase-A epilogue settles ----
    const char* gfb = reinterpret_cast<const char*>(g_face4);
    {
        unsigned int sb = smem_u32(&s_face[0][0]);
#pragma unroll
        for (int k = 0; k < 4; k++) {
            int off = (tid + k * 256) * 16;
            cp16(sb + off, gfb + off);
        }
        asm volatile("cp.async.commit_group;" ::: "memory");
    }
    __syncthreads();

    // ---- Phase B: parity over faces; records read from smem tiles ----
    float4 po = s_po[lane];
    float4 pd = s_pd[lane];

    u64 OX = pk(po.x, po.x), OY = pk(po.y, po.y), OZ = pk(po.z, po.z);
    u64 DX = pk(pd.x, pd.x), DY = pk(pd.y, pd.y), DZ = pk(pd.z, pd.z);
    u64 NEG1 = pk(-1.0f, -1.0f);
    u64 MEPS = pk(-EPSF, -EPSF);
    u64 NEGQ = pk(-EPSQ, -EPSQ);

    int cnt = 0;

    for (int t = 0; t < NTILE; t++) {
        // prefetch next tile into the other buffer
        if (t + 1 < NTILE) {
            unsigned int sb = smem_u32(&s_face[(t + 1) & 1][0]);
            const char* gsrc = gfb + (t + 1) * TILE_BYTES;
#pragma unroll
            for (int k = 0; k < 4; k++) {
                int off = (tid + k * 256) * 16;
                cp16(sb + off, gsrc + off);
            }
            asm volatile("cp.async.commit_group;" ::: "memory");
            asm volatile("cp.async.wait_group 1;" ::: "memory");
        } else {
            asm volatile("cp.async.wait_group 0;" ::: "memory");
        }
        __syncthreads();

        const ulonglong2* up = reinterpret_cast<const ulonglong2*>(
            &s_face[t & 1][0]) + (wid * PAIRS_PER_WARP) * 8;

#pragma unroll 2
        for (int lp = 0; lp < PAIRS_PER_WARP; lp++, up += 8) {
            ulonglong2 t0 = up[0];
            ulonglong2 t1 = up[1];

            // normal block
            u64 no  = f2fma(t0.x, OX, f2fma(t0.y, OY, f2mul(t1.x, OZ)));
            u64 num = f2fma(no, NEG1, t1.y);
            u64 den = f2fma(t0.x, DX, f2fma(t0.y, DY, f2mul(t1.x, DZ)));

            // edge A
            ulonglong2 t2 = up[2];
            ulonglong2 t3 = up[3];
            u64 ba = f2fma(t2.x, OX, f2fma(t2.y, OY, f2fma(t3.x, OZ, t3.y)));
            u64 da = f2fma(t2.x, DX, f2fma(t2.y, DY, f2mul(t3.x, DZ)));
            u64 ra = f2mul(f2fma(ba, den, f2mul(num, da)), den);

            // edge B
            ulonglong2 t4 = up[4];
            ulonglong2 t5 = up[5];
            u64 bb_ = f2fma(t4.x, OX, f2fma(t4.y, OY, f2fma(t5.x, OZ, t5.y)));
            u64 db  = f2fma(t4.x, DX, f2fma(t4.y, DY, f2mul(t5.x, DZ)));
            u64 rb  = f2mul(f2fma(bb_, den, f2mul(num, db)), den);

            // edge C
            ulonglong2 t6 = up[6];
            ulonglong2 t7 = up[7];
            u64 bc = f2fma(t6.x, OX, f2fma(t6.y, OY, f2fma(t7.x, OZ, t7.y)));
            u64 dc = f2fma(t6.x, DX, f2fma(t6.y, DY, f2mul(t7.x, DZ)));
            u64 rc = f2mul(f2fma(bc, den, f2mul(num, dc)), den);

            u64 wv  = f2mul(f2fma(MEPS, den, num), den);   // >0 <=> t>EPS
            u64 ddq = f2fma(den, den, NEGQ);               // >0 <=> |den|>EPS

            float ra0, ra1, rb0, rb1, rc0, rc1, w0, w1, q0, q1;
            upk(ra, ra0, ra1);
            upk(rb, rb0, rb1);
            upk(rc, rc0, rc1);
            upk(wv, w0, w1);
            upk(ddq, q0, q1);

            float m0 = fminf(fminf(ra0, rb0), fminf(rc0, fminf(w0, q0)));
            float m1 = fminf(fminf(ra1, rb1), fminf(rc1, fminf(w1, q1)));
            cnt += (m0 > 0.0f) ? 1 : 0;
            cnt += (m1 > 0.0f) ? 1 : 0;
        }
        __syncthreads();   // all warps done with this buffer before overwrite
    }

    s_cnt[wid][lane] = cnt;
    __syncthreads();

    if (wid == 0) {
        int tot = 0;
#pragma unroll
        for (int k = 0; k < 8; k++) tot += s_cnt[k][lane];
        float pen = (tot & 1) ? s_pd[lane].w : 0.0f;
#pragma unroll
        for (int off = 16; off; off >>= 1)
            pen += __shfl_down_sync(~0u, pen, off);
        if (lane == 0) {
            g_part[blockIdx.x] = pen;
            __threadfence();
            unsigned int t = atomicAdd(&g_ctr, 1u);
            s_last = (t == NBLK - 1) ? 1 : 0;
        }
    }
    __syncthreads();

    // ---- last block: deterministic final reduction over 256 partials ----
    if (s_last) {
        float v;
        asm volatile("ld.global.cg.f32 %0, [%1];" : "=f"(v)
                     : "l"(&g_part[threadIdx.x]));
        s_red[threadIdx.x] = v;
        __syncthreads();
#pragma unroll
        for (int off = 128; off; off >>= 1) {
            if (threadIdx.x < off) s_red[threadIdx.x] += s_red[threadIdx.x + off];
            __syncthreads();
        }
        if (threadIdx.x == 0) out[0] = sqrtf(s_red[0] + 1e-12f);
    }
}

// ---------------- launch ---------------------------------------------------
extern "C" void kernel_launch(void* const* d_in, const int* in_sizes, int n_in,
                              void* d_out, int out_size) {
    const float* obj = (const float*)d_in[0];
    const float* sr  = (const float*)d_in[1];
    const float* hv  = (const float*)d_in[2];
    const float* fn  = (const float*)d_in[3];
    const int*   hf  = (const int*)d_in[4];
    float* out = (float*)d_out;

    prep_kernel<<<(N_F + 255) / 256, 256>>>(sr, hv, fn, hf);
    main_kernel<<<NBLK, 256>>>(obj, out);
}

// round 8
// speedup vs baseline: 1.2013x; 1.0263x over previous
#include <cuda_runtime.h>

// SR_Loss: NN(obj->sr) + ray-triangle parity interior test + reductions.
// obj 8192x3, sr 4096x3, verts 4100x3, normals 4096x3, faces 4096x3.
// Output: [pen_dist, cmap(8192)] = 8193 f32.
//
// 2 kernels: prep (face constants + sr packing + counter reset),
// main (fused NN + parity + last-block final reduction), 512 thr/block.
// Phase B: smem-tiled face records (cp.async double buffer), f32x2 packed
// math (2 faces/lane-op), sign-match hit test (no divisions, no x*den muls).

#define N_OBJ  8192
#define N_SR   4096
#define N_F    4096
#define NPAIR  (N_F / 2)
#define EPSF   1e-8f
#define NBLK   (N_OBJ / 32)

#define NWARP  16                        // warps per block
#define TILE_P     128                   // face-pairs per smem tile
#define NTILE      (NPAIR / TILE_P)      // 16
#define TILE_BYTES (TILE_P * 128)        // 16 KB
#define PAIRS_PER_WARP (TILE_P / NWARP)  // 8

typedef unsigned long long u64;

// ---------------- scratch (device globals; no allocation allowed) ----------
__device__ float4 g_sr4[N_SR];          // sr point + |s|^2
__device__ float4 g_face4[NPAIR * 8];   // pair-interleaved face constants (32 f/pair)
__device__ float  g_part[NBLK];         // per-block pen partial sums
__device__ unsigned int g_ctr;          // arrival counter for last-block reduce

// ---------------- f32x2 packed helpers (sm_103a) ---------------------------
__device__ __forceinline__ u64 pk(float lo, float hi) {
    u64 r;
    asm("mov.b64 %0, {%1, %2};" : "=l"(r)
        : "r"(__float_as_uint(lo)), "r"(__float_as_uint(hi)));
    return r;
}
__device__ __forceinline__ void upku(u64 v, unsigned int& lo, unsigned int& hi) {
    asm("mov.b64 {%0, %1}, %2;" : "=r"(lo), "=r"(hi) : "l"(v));
}
__device__ __forceinline__ u64 f2mul(u64 a, u64 b) {
    u64 r;
    asm("mul.rn.f32x2 %0, %1, %2;" : "=l"(r) : "l"(a), "l"(b));
    return r;
}
__device__ __forceinline__ u64 f2fma(u64 a, u64 b, u64 c) {
    u64 r;
    asm("fma.rn.f32x2 %0, %1, %2, %3;" : "=l"(r) : "l"(a), "l"(b), "l"(c));
    return r;
}

// cp.async 16B chunk: gmem -> smem (L2 path, no intermediate registers)
__device__ __forceinline__ void cp16(unsigned int saddr, const void* gaddr) {
    asm volatile("cp.async.cg.shared.global [%0], [%1], 16;"
                 :: "r"(saddr), "l"(gaddr));
}
__device__ __forceinline__ unsigned int smem_u32(const void* p) {
    return (unsigned int)__cvta_generic_to_shared(p);
}

// ---------------- prep: pack sr, precompute face constants -----------------
// Face record (16 floats): n(3), v0.n, c01(3), -v0.c01, c12(3), -v1.c12,
// c20(3), -v2.c20, c_ab = cross(n, vb - va). Pair-interleaved: for pair p,
// slot q at float index p*32 + 2*q + (f&1) -> one 16B load = two f32x2 operands.
__global__ void prep_kernel(const float* __restrict__ sr,
                            const float* __restrict__ hv,
                            const float* __restrict__ fn,
                            const int*   __restrict__ hf) {
    int f = blockIdx.x * blockDim.x + threadIdx.x;
    if (f == 0) g_ctr = 0;
    if (f >= N_F) return;

    float sx = sr[3 * f + 0], sy = sr[3 * f + 1], sz = sr[3 * f + 2];
    g_sr4[f] = make_float4(sx, sy, sz, sx * sx + sy * sy + sz * sz);

    int i0 = hf[3 * f + 0], i1 = hf[3 * f + 1], i2 = hf[3 * f + 2];
    float nx = fn[3 * f + 0], ny = fn[3 * f + 1], nz = fn[3 * f + 2];
    float v0x = hv[3 * i0 + 0], v0y = hv[3 * i0 + 1], v0z = hv[3 * i0 + 2];
    float v1x = hv[3 * i1 + 0], v1y = hv[3 * i1 + 1], v1z = hv[3 * i1 + 2];
    float v2x = hv[3 * i2 + 0], v2y = hv[3 * i2 + 1], v2z = hv[3 * i2 + 2];

    float vals[16];
    vals[0] = nx; vals[1] = ny; vals[2] = nz;
    vals[3] = v0x * nx + v0y * ny + v0z * nz;
    {
        float wx = v1x - v0x, wy = v1y - v0y, wz = v1z - v0z;
        float cx = ny * wz - nz * wy, cy = nz * wx - nx * wz, cz = nx * wy - ny * wx;
        vals[4] = cx; vals[5] = cy; vals[6] = cz;
        vals[7] = -(v0x * cx + v0y * cy + v0z * cz);
    }
    {
        float wx = v2x - v1x, wy = v2y - v1y, wz = v2z - v1z;
        float cx = ny * wz - nz * wy, cy = nz * wx - nx * wz, cz = nx * wy - ny * wx;
        vals[8] = cx; vals[9] = cy; vals[10] = cz;
        vals[11] = -(v1x * cx + v1y * cy + v1z * cz);
    }
    {
        float wx = v0x - v2x, wy = v0y - v2y, wz = v0z - v2z;
        float cx = ny * wz - nz * wy, cy = nz * wx - nx * wz, cz = nx * wy - ny * wx;
        vals[12] = cx; vals[13] = cy; vals[14] = cz;
        vals[15] = -(v2x * cx + v2y * cy + v2z * cz);
    }

    int p = f >> 1, h = f & 1;
    float* out = reinterpret_cast<float*>(g_face4) + p * 32 + h;
#pragma unroll
    for (int q = 0; q < 16; q++) out[2 * q] = vals[q];
}

// ---------------- main: fused NN + cmap + parity + full reduction ----------
__global__ void __launch_bounds__(512, 2) main_kernel(const float* __restrict__ obj,
                                                      float* __restrict__ out) {
    __shared__ __align__(16) char s_face[2][TILE_BYTES];   // 32 KB double buffer
    __shared__ float4 s_po[32];   // point o
    __shared__ float4 s_pd[32];   // D = trg - o, .w = |D|^2
    __shared__ int    s_cnt[NWARP][32];
    __shared__ int    s_last;
    __shared__ float  s_red[512];

    int tid = threadIdx.x;
    int wid = tid >> 5, lane = tid & 31;
    int pbase = blockIdx.x * 32 + wid * 2;   // 2 points per warp

    // ---- Phase A: NN for 2 points per warp ----
    float ox0 = obj[3 * (pbase + 0) + 0], oy0 = obj[3 * (pbase + 0) + 1], oz0 = obj[3 * (pbase + 0) + 2];
    float ox1 = obj[3 * (pbase + 1) + 0], oy1 = obj[3 * (pbase + 1) + 1], oz1 = obj[3 * (pbase + 1) + 2];
    float o20 = ox0 * ox0 + oy0 * oy0 + oz0 * oz0;
    float o21 = ox1 * ox1 + oy1 * oy1 + oz1 * oz1;

    float b0 = 3.402823466e38f, b1 = b0;
    int j0 = 0, j1 = 0;

#pragma unroll 4
    for (int j = lane; j < N_SR; j += 32) {
        float4 s = __ldg(&g_sr4[j]);
        float d0 = fmaf(-2.0f, ox0 * s.x + fmaf(oy0, s.y, oz0 * s.z), o20 + s.w);
        float d1 = fmaf(-2.0f, ox1 * s.x + fmaf(oy1, s.y, oz1 * s.z), o21 + s.w);
        if (d0 < b0) { b0 = d0; j0 = j; }
        if (d1 < b1) { b1 = d1; j1 = j; }
    }
#pragma unroll
    for (int off = 16; off; off >>= 1) {
        float t; int tj;
        t = __shfl_down_sync(~0u, b0, off); tj = __shfl_down_sync(~0u, j0, off);
        if (t < b0 || (t == b0 && tj < j0)) { b0 = t; j0 = tj; }
        t = __shfl_down_sync(~0u, b1, off); tj = __shfl_down_sync(~0u, j1, off);
        if (t < b1 || (t == b1 && tj < j1)) { b1 = t; j1 = tj; }
    }

    if (lane == 0) {
        float obx[2] = {ox0, ox1};
        float oby[2] = {oy0, oy1};
        float obz[2] = {oz0, oz1};
        float bb[2] = {b0, b1};
        int   jj[2] = {j0, j1};
#pragma unroll
        for (int k = 0; k < 2; k++) {
            float4 s = g_sr4[jj[k]];
            float Dx = s.x - obx[k], Dy = s.y - oby[k], Dz = s.z - obz[k];
            s_po[wid * 2 + k] = make_float4(obx[k], oby[k], obz[k], 0.0f);
            s_pd[wid * 2 + k] = make_float4(Dx, Dy, Dz, Dx * Dx + Dy * Dy + Dz * Dz);
            float nnd = sqrtf(fmaxf(bb[k], 0.0f));
            out[1 + pbase + k] = 2.0f / (1.0f + expf(100.0f * nnd));
        }
    }

    // ---- stage tile 0 (1024 x 16B chunks over 512 threads) ----
    const char* gfb = reinterpret_cast<const char*>(g_face4);
    {
        unsigned int sb = smem_u32(&s_face[0][0]);
#pragma unroll
        for (int k = 0; k < 2; k++) {
            int off = (tid + k * 512) * 16;
            cp16(sb + off, gfb + off);
        }
        asm volatile("cp.async.commit_group;" ::: "memory");
    }
    __syncthreads();

    // ---- Phase B: parity over faces; records read from smem tiles ----
    float4 po = s_po[lane];
    float4 pd = s_pd[lane];

    u64 OX = pk(po.x, po.x), OY = pk(po.y, po.y), OZ = pk(po.z, po.z);
    u64 DX = pk(pd.x, pd.x), DY = pk(pd.y, pd.y), DZ = pk(pd.z, pd.z);
    u64 NEG1 = pk(-1.0f, -1.0f);
    u64 MEPS = pk(-EPSF, -EPSF);
    const unsigned int EPS_BITS = __float_as_uint(EPSF);

    int cnt = 0;

    for (int t = 0; t < NTILE; t++) {
        // prefetch next tile into the other buffer
        if (t + 1 < NTILE) {
            unsigned int sb = smem_u32(&s_face[(t + 1) & 1][0]);
            const char* gsrc = gfb + (t + 1) * TILE_BYTES;
#pragma unroll
            for (int k = 0; k < 2; k++) {
                int off = (tid + k * 512) * 16;
                cp16(sb + off, gsrc + off);
            }
            asm volatile("cp.async.commit_group;" ::: "memory");
            asm volatile("cp.async.wait_group 1;" ::: "memory");
        } else {
            asm volatile("cp.async.wait_group 0;" ::: "memory");
        }
        __syncthreads();

        const ulonglong2* up = reinterpret_cast<const ulonglong2*>(
            &s_face[t & 1][0]) + (wid * PAIRS_PER_WARP) * 8;

#pragma unroll 2
        for (int lp = 0; lp < PAIRS_PER_WARP; lp++, up += 8) {
            ulonglong2 t0 = up[0];
            ulonglong2 t1 = up[1];

            // normal block:  num = v0.n - n.o   den = n.D
            u64 no  = f2fma(t0.x, OX, f2fma(t0.y, OY, f2mul(t1.x, OZ)));
            u64 num = f2fma(no, NEG1, t1.y);
            u64 den = f2fma(t0.x, DX, f2fma(t0.y, DY, f2mul(t1.x, DZ)));

            // edge A:  qa = base_a*den + num*bd_a   (sign(qa)==sign(den) <=> s_a>=0)
            ulonglong2 t2 = up[2];
            ulonglong2 t3 = up[3];
            u64 ba = f2fma(t2.x, OX, f2fma(t2.y, OY, f2fma(t3.x, OZ, t3.y)));
            u64 da = f2fma(t2.x, DX, f2fma(t2.y, DY, f2mul(t3.x, DZ)));
            u64 qa = f2fma(ba, den, f2mul(num, da));

            // edge B
            ulonglong2 t4 = up[4];
            ulonglong2 t5 = up[5];
            u64 bb_ = f2fma(t4.x, OX, f2fma(t4.y, OY, f2fma(t5.x, OZ, t5.y)));
            u64 db  = f2fma(t4.x, DX, f2fma(t4.y, DY, f2mul(t5.x, DZ)));
            u64 qb  = f2fma(bb_, den, f2mul(num, db));

            // edge C
            ulonglong2 t6 = up[6];
            ulonglong2 t7 = up[7];
            u64 bc = f2fma(t6.x, OX, f2fma(t6.y, OY, f2fma(t7.x, OZ, t7.y)));
            u64 dc = f2fma(t6.x, DX, f2fma(t6.y, DY, f2mul(t7.x, DZ)));
            u64 qc = f2fma(bc, den, f2mul(num, dc));

            // w = num - EPS*den  (sign(w)==sign(den) <=> t>EPS)
            u64 wv = f2fma(MEPS, den, num);

            // sign-match hit test, per packed half (bit ops on ALU pipe):
            // hit = sign(qa)=sign(qb)=sign(qc)=sign(w)=sign(den) && |den|>EPS
            unsigned int qa0, qa1, qb0, qb1, qc0, qc1, w0, w1, d0, d1;
            upku(qa, qa0, qa1);
            upku(qb, qb0, qb1);
            upku(qc, qc0, qc1);
            upku(wv, w0, w1);
            upku(den, d0, d1);

            unsigned int x0 = ((qa0 ^ d0) | (qb0 ^ d0)) | ((qc0 ^ d0) | (w0 ^ d0));
            unsigned int x1 = ((qa1 ^ d1) | (qb1 ^ d1)) | ((qc1 ^ d1) | (w1 ^ d1));
            cnt += (int)(((int)x0 >= 0) & ((d0 & 0x7fffffffu) > EPS_BITS));
            cnt += (int)(((int)x1 >= 0) & ((d1 & 0x7fffffffu) > EPS_BITS));
        }
        __syncthreads();   // all warps done with this buffer before overwrite
    }

    s_cnt[wid][lane] = cnt;
    __syncthreads();

    if (wid == 0) {
        int tot = 0;
#pragma unroll
        for (int k = 0; k < NWARP; k++) tot += s_cnt[k][lane];
        float pen = (tot & 1) ? s_pd[lane].w : 0.0f;
#pragma unroll
        for (int off = 16; off; off >>= 1)
            pen += __shfl_down_sync(~0u, pen, off);
        if (lane == 0) {
            g_part[blockIdx.x] = pen;
            __threadfence();
            unsigned int t = atomicAdd(&g_ctr, 1u);
            s_last = (t == NBLK - 1) ? 1 : 0;
        }
    }
    __syncthreads();

    // ---- last block: deterministic final reduction over 256 partials ----
    if (s_last) {
        float v = 0.0f;
        if (tid < NBLK) {
            asm volatile("ld.global.cg.f32 %0, [%1];" : "=f"(v)
                         : "l"(&g_part[tid]));
        }
        s_red[tid] = v;
        __syncthreads();
#pragma unroll
        for (int off = 256; off; off >>= 1) {
            if (tid < off) s_red[tid] += s_red[tid + off];
            __syncthreads();
        }
        if (tid == 0) out[0] = sqrtf(s_red[0] + 1e-12f);
    }
}

// ---------------- launch ---------------------------------------------------
extern "C" void kernel_launch(void* const* d_in, const int* in_sizes, int n_in,
                              void* d_out, int out_size) {
    const float* obj = (const float*)d_in[0];
    const float* sr  = (const float*)d_in[1];
    const float* hv  = (const float*)d_in[2];
    const float* fn  = (const float*)d_in[3];
    const int*   hf  = (const int*)d_in[4];
    float* out = (float*)d_out;

    prep_kernel<<<32, 128>>>(sr, hv, fn, hf);
    main_kernel<<<NBLK, 512>>>(obj, out);
}

// round 9
// speedup vs baseline: 1.3700x; 1.1405x over previous
#include <cuda_runtime.h>

// SR_Loss: NN(obj->sr) + ray-triangle parity interior test + reductions.
// obj 8192x3, sr 4096x3, verts 4100x3, normals 4096x3, faces 4096x3.
// Output: [pen_dist, cmap(8192)] = 8193 f32.
//
// 3 kernels:
//  prep : face constants (28 f/pair, edge-C eliminated by identity) + sr pack
//         + zero hit counters.
//  nn   : balanced NN -> g_D4, cmap.
//  hits : 1024 blocks = 256 point-groups x 4 face-quarters; smem-tiled face
//         records, f32x2 packed sign tests; int atomics for hit counts
//         (deterministic); group-last computes pen partial; global-last
//         reduces to pen_dist.

#define N_OBJ  8192
#define N_SR   4096
#define N_F    4096
#define NPAIR  (N_F / 2)          // 2048
#define EPSF   1e-8f
#define NGRP   (N_OBJ / 32)       // 256 point groups
#define NFQ    4                  // face quarters per group
#define PAIRS_PER_FQ (NPAIR / NFQ) // 512

#define TILE_P     128
#define NTILE_FQ   (PAIRS_PER_FQ / TILE_P)   // 4
#define REC_U      7                          // ulonglong2 per pair record
#define TILE_BYTES (TILE_P * REC_U * 16)      // 14336
#define CHUNKS     (TILE_BYTES / 16)          // 896

typedef unsigned long long u64;

// ---------------- scratch (device globals; no allocation allowed) ----------
__device__ float4 g_sr4[N_SR];              // sr point + |s|^2
__device__ float4 g_face4[NPAIR * REC_U];   // pair-interleaved records (28 f/pair)
__device__ float4 g_D4[N_OBJ];              // D = trg - o, .w = |D|^2
__device__ int    g_hits[N_OBJ];            // accumulated hit counts
__device__ float  g_part[NGRP];             // per-group pen partials
__device__ unsigned int g_gctr[NGRP];       // per-group arrival counters
__device__ unsigned int g_ctr;              // global arrival counter

// ---------------- f32x2 packed helpers (sm_103a) ---------------------------
__device__ __forceinline__ u64 pk(float lo, float hi) {
    u64 r;
    asm("mov.b64 %0, {%1, %2};" : "=l"(r)
        : "r"(__float_as_uint(lo)), "r"(__float_as_uint(hi)));
    return r;
}
__device__ __forceinline__ void upku(u64 v, unsigned int& lo, unsigned int& hi) {
    asm("mov.b64 {%0, %1}, %2;" : "=r"(lo), "=r"(hi) : "l"(v));
}
__device__ __forceinline__ u64 f2mul(u64 a, u64 b) {
    u64 r;
    asm("mul.rn.f32x2 %0, %1, %2;" : "=l"(r) : "l"(a), "l"(b));
    return r;
}
__device__ __forceinline__ u64 f2add(u64 a, u64 b) {
    u64 r;
    asm("add.rn.f32x2 %0, %1, %2;" : "=l"(r) : "l"(a), "l"(b));
    return r;
}
__device__ __forceinline__ u64 f2fma(u64 a, u64 b, u64 c) {
    u64 r;
    asm("fma.rn.f32x2 %0, %1, %2, %3;" : "=l"(r) : "l"(a), "l"(b), "l"(c));
    return r;
}
__device__ __forceinline__ void cp16(unsigned int saddr, const void* gaddr) {
    asm volatile("cp.async.cg.shared.global [%0], [%1], 16;"
                 :: "r"(saddr), "l"(gaddr));
}
__device__ __forceinline__ unsigned int smem_u32(const void* p) {
    return (unsigned int)__cvta_generic_to_shared(p);
}

// ---------------- prep -----------------------------------------------------
// Pair record, 14 slots of f32x2 (28 floats, 112B):
//  q0-2: n, q3: v0.n, q4-6: C01, q7: e01, q8-10: C12, q11: e12,
//  q12: E = e01+e12+e20, q13: pad.   (C20 = -(C01+C12) by identity.)
// float index for face f = pair p half h: p*28 + 2q + h.
__global__ void prep_kernel(const float* __restrict__ sr,
                            const float* __restrict__ hv,
                            const float* __restrict__ fn,
                            const int*   __restrict__ hf) {
    int f = blockIdx.x * blockDim.x + threadIdx.x;   // 0..4095
    if (f == 0) g_ctr = 0;
    if (f < NGRP) g_gctr[f] = 0;
    g_hits[f] = 0;
    g_hits[f + N_F] = 0;
    if (f >= N_F) return;

    float sx = sr[3 * f + 0], sy = sr[3 * f + 1], sz = sr[3 * f + 2];
    g_sr4[f] = make_float4(sx, sy, sz, sx * sx + sy * sy + sz * sz);

    int i0 = hf[3 * f + 0], i1 = hf[3 * f + 1], i2 = hf[3 * f + 2];
    float nx = fn[3 * f + 0], ny = fn[3 * f + 1], nz = fn[3 * f + 2];
    float v0x = hv[3 * i0 + 0], v0y = hv[3 * i0 + 1], v0z = hv[3 * i0 + 2];
    float v1x = hv[3 * i1 + 0], v1y = hv[3 * i1 + 1], v1z = hv[3 * i1 + 2];
    float v2x = hv[3 * i2 + 0], v2y = hv[3 * i2 + 1], v2z = hv[3 * i2 + 2];

    float vals[14];
    vals[0] = nx; vals[1] = ny; vals[2] = nz;
    vals[3] = v0x * nx + v0y * ny + v0z * nz;

    float eA, eB, eC;
    {   // edge 01
        float wx = v1x - v0x, wy = v1y - v0y, wz = v1z - v0z;
        float cx = ny * wz - nz * wy, cy = nz * wx - nx * wz, cz = nx * wy - ny * wx;
        vals[4] = cx; vals[5] = cy; vals[6] = cz;
        eA = -(v0x * cx + v0y * cy + v0z * cz);
        vals[7] = eA;
    }
    {   // edge 12
        float wx = v2x - v1x, wy = v2y - v1y, wz = v2z - v1z;
        float cx = ny * wz - nz * wy, cy = nz * wx - nx * wz, cz = nx * wy - ny * wx;
        vals[8] = cx; vals[9] = cy; vals[10] = cz;
        eB = -(v1x * cx + v1y * cy + v1z * cz);
        vals[11] = eB;
    }
    {   // edge 20 (only its offset is needed)
        float wx = v0x - v2x, wy = v0y - v2y, wz = v0z - v2z;
        float cx = ny * wz - nz * wy, cy = nz * wx - nx * wz, cz = nx * wy - ny * wx;
        eC = -(v2x * cx + v2y * cy + v2z * cz);
    }
    vals[12] = eA + eB + eC;
    vals[13] = 0.0f;

    int p = f >> 1, h = f & 1;
    float* out = reinterpret_cast<float*>(g_face4) + p * 28 + h;
#pragma unroll
    for (int q = 0; q < 14; q++) out[2 * q] = vals[q];
}

// ---------------- nn: NN + cmap + D ----------------------------------------
// 512 blocks x 256 thr; 16 points/block, 2 points/warp.
__global__ void __launch_bounds__(256) nn_kernel(const float* __restrict__ obj,
                                                 float* __restrict__ out) {
    int wid = threadIdx.x >> 5, lane = threadIdx.x & 31;
    int pbase = blockIdx.x * 16 + wid * 2;

    float ox0 = obj[3 * (pbase + 0) + 0], oy0 = obj[3 * (pbase + 0) + 1], oz0 = obj[3 * (pbase + 0) + 2];
    float ox1 = obj[3 * (pbase + 1) + 0], oy1 = obj[3 * (pbase + 1) + 1], oz1 = obj[3 * (pbase + 1) + 2];
    float o20 = ox0 * ox0 + oy0 * oy0 + oz0 * oz0;
    float o21 = ox1 * ox1 + oy1 * oy1 + oz1 * oz1;

    float b0 = 3.402823466e38f, b1 = b0;
    int j0 = 0, j1 = 0;

#pragma unroll 4
    for (int j = lane; j < N_SR; j += 32) {
        float4 s = __ldg(&g_sr4[j]);
        float d0 = fmaf(-2.0f, ox0 * s.x + fmaf(oy0, s.y, oz0 * s.z), o20 + s.w);
        float d1 = fmaf(-2.0f, ox1 * s.x + fmaf(oy1, s.y, oz1 * s.z), o21 + s.w);
        if (d0 < b0) { b0 = d0; j0 = j; }
        if (d1 < b1) { b1 = d1; j1 = j; }
    }
#pragma unroll
    for (int off = 16; off; off >>= 1) {
        float t; int tj;
        t = __shfl_down_sync(~0u, b0, off); tj = __shfl_down_sync(~0u, j0, off);
        if (t < b0 || (t == b0 && tj < j0)) { b0 = t; j0 = tj; }
        t = __shfl_down_sync(~0u, b1, off); tj = __shfl_down_sync(~0u, j1, off);
        if (t < b1 || (t == b1 && tj < j1)) { b1 = t; j1 = tj; }
    }

    if (lane == 0) {
        float obx[2] = {ox0, ox1};
        float oby[2] = {oy0, oy1};
        float obz[2] = {oz0, oz1};
        float bb[2] = {b0, b1};
        int   jj[2] = {j0, j1};
#pragma unroll
        for (int k = 0; k < 2; k++) {
            float4 s = g_sr4[jj[k]];
            float Dx = s.x - obx[k], Dy = s.y - oby[k], Dz = s.z - obz[k];
            g_D4[pbase + k] = make_float4(Dx, Dy, Dz, Dx * Dx + Dy * Dy + Dz * Dz);
            float nnd = sqrtf(fmaxf(bb[k], 0.0f));
            out[1 + pbase + k] = 2.0f / (1.0f + expf(100.0f * nnd));
        }
    }
}

// ---------------- hits: parity + reductions --------------------------------
// Block = (group, quarter): 32 points (lane=point) x 512 face-pairs.
__global__ void __launch_bounds__(256, 4) hits_kernel(const float* __restrict__ obj,
                                                      float* __restrict__ out) {
    __shared__ __align__(16) char s_face[2][TILE_BYTES];   // 2 x 14 KB
    __shared__ int    s_cnt[8][32];
    __shared__ int    s_glast, s_last;
    __shared__ float  s_red[256];

    int tid = threadIdx.x;
    int wid = tid >> 5, lane = tid & 31;
    int grp = blockIdx.x >> 2, fq = blockIdx.x & 3;
    int pt  = grp * 32 + lane;

    float ox = obj[3 * pt + 0], oy = obj[3 * pt + 1], oz = obj[3 * pt + 2];
    float4 D = __ldg(&g_D4[pt]);

    u64 OX = pk(ox, ox), OY = pk(oy, oy), OZ = pk(oz, oz);
    u64 DX = pk(D.x, D.x), DY = pk(D.y, D.y), DZ = pk(D.z, D.z);
    u64 NEG1 = pk(-1.0f, -1.0f);
    u64 MEPS = pk(-EPSF, -EPSF);
    const unsigned int EPS_BITS = __float_as_uint(EPSF);

    const char* gfb = reinterpret_cast<const char*>(g_face4)
                      + (size_t)fq * PAIRS_PER_FQ * REC_U * 16;

    // stage tile 0
    {
        unsigned int sb = smem_u32(&s_face[0][0]);
#pragma unroll
        for (int k = 0; k < 4; k++) {
            int idx = tid + k * 256;
            if (idx < CHUNKS) cp16(sb + idx * 16, gfb + idx * 16);
        }
        asm volatile("cp.async.commit_group;" ::: "memory");
    }

    int cnt = 0;

    for (int t = 0; t < NTILE_FQ; t++) {
        if (t + 1 < NTILE_FQ) {
            unsigned int sb = smem_u32(&s_face[(t + 1) & 1][0]);
            const char* gsrc = gfb + (t + 1) * TILE_BYTES;
#pragma unroll
            for (int k = 0; k < 4; k++) {
                int idx = tid + k * 256;
                if (idx < CHUNKS) cp16(sb + idx * 16, gsrc + idx * 16);
            }
            asm volatile("cp.async.commit_group;" ::: "memory");
            asm volatile("cp.async.wait_group 1;" ::: "memory");
        } else {
            asm volatile("cp.async.wait_group 0;" ::: "memory");
        }
        __syncthreads();

        const ulonglong2* up = reinterpret_cast<const ulonglong2*>(
            &s_face[t & 1][0]) + (wid * (TILE_P / 8)) * REC_U;

#pragma unroll 2
        for (int lp = 0; lp < TILE_P / 8; lp++, up += REC_U) {
            ulonglong2 t0 = up[0];   // nx | ny
            ulonglong2 t1 = up[1];   // nz | v0n
            ulonglong2 t2 = up[2];   // CAx | CAy
            ulonglong2 t3 = up[3];   // CAz | eA
            ulonglong2 t4 = up[4];   // CBx | CBy
            ulonglong2 t5 = up[5];   // CBz | eB
            u64 Ev = up[6].x;        // E (f32x2)

            // normal block
            u64 no   = f2fma(t0.x, OX, f2fma(t0.y, OY, f2mul(t1.x, OZ)));
            u64 num  = f2fma(no, NEG1, t1.y);      // v0n - n.o
            u64 numn = f2fma(t1.y, NEG1, no);      // n.o - v0n
            u64 den  = f2fma(t0.x, DX, f2fma(t0.y, DY, f2mul(t1.x, DZ)));

            // edge A
            u64 ba = f2fma(t2.x, OX, f2fma(t2.y, OY, f2fma(t3.x, OZ, t3.y)));
            u64 da = f2fma(t2.x, DX, f2fma(t2.y, DY, f2mul(t3.x, DZ)));
            u64 qa = f2fma(ba, den, f2mul(num, da));

            // edge B
            u64 bb_ = f2fma(t4.x, OX, f2fma(t4.y, OY, f2fma(t5.x, OZ, t5.y)));
            u64 db  = f2fma(t4.x, DX, f2fma(t4.y, DY, f2mul(t5.x, DZ)));
            u64 qb  = f2fma(bb_, den, f2mul(num, db));

            // edge C by identity: bc = E - ba - bb, dc = -(da+db)
            u64 sab = f2add(da, db);
            u64 tab = f2add(ba, bb_);
            u64 bc  = f2fma(tab, NEG1, Ev);
            u64 qc  = f2fma(bc, den, f2mul(numn, sab));

            // w = num - EPS*den
            u64 wv = f2fma(MEPS, den, num);

            unsigned int qa0, qa1, qb0, qb1, qc0, qc1, w0, w1, d0, d1;
            upku(qa, qa0, qa1);
            upku(qb, qb0, qb1);
            upku(qc, qc0, qc1);
            upku(wv, w0, w1);
            upku(den, d0, d1);

            unsigned int x0 = ((qa0 ^ d0) | (qb0 ^ d0)) | ((qc0 ^ d0) | (w0 ^ d0));
            unsigned int x1 = ((qa1 ^ d1) | (qb1 ^ d1)) | ((qc1 ^ d1) | (w1 ^ d1));
            cnt += (int)(((int)x0 >= 0) & ((d0 & 0x7fffffffu) > EPS_BITS));
            cnt += (int)(((int)x1 >= 0) & ((d1 & 0x7fffffffu) > EPS_BITS));
        }
        __syncthreads();
    }

    s_cnt[wid][lane] = cnt;
    __syncthreads();

    // warp 0 accumulates this block's per-point counts into gmem (int = exact)
    if (wid == 0) {
        int tot = 0;
#pragma unroll
        for (int k = 0; k < 8; k++) tot += s_cnt[k][lane];
        atomicAdd(&g_hits[pt], tot);
    }

    // group completion
    if (tid == 0) {
        __threadfence();
        unsigned int a = atomicAdd(&g_gctr[grp], 1u);
        s_glast = (a == NFQ - 1) ? 1 : 0;
        s_last = 0;
    }
    __syncthreads();

    if (s_glast) {
        if (wid == 0) {
            int tot;
            asm volatile("ld.global.cg.s32 %0, [%1];" : "=r"(tot)
                         : "l"(&g_hits[pt]));
            float dw;
            asm volatile("ld.global.cg.f32 %0, [%1];" : "=f"(dw)
                         : "l"(reinterpret_cast<const float*>(&g_D4[pt]) + 3));
            float pen = (tot & 1) ? dw : 0.0f;
#pragma unroll
            for (int off = 16; off; off >>= 1)
                pen += __shfl_down_sync(~0u, pen, off);
            if (lane == 0) {
                g_part[grp] = pen;
                __threadfence();
                unsigned int a = atomicAdd(&g_ctr, 1u);
                if (a == NGRP - 1) s_last = 1;
            }
        }
        __syncthreads();

        if (s_last) {
            float v;
            asm volatile("ld.global.cg.f32 %0, [%1];" : "=f"(v)
                         : "l"(&g_part[tid]));
            s_red[tid] = v;
            __syncthreads();
#pragma unroll
            for (int off = 128; off; off >>= 1) {
                if (tid < off) s_red[tid] += s_red[tid + off];
                __syncthreads();
            }
            if (tid == 0) out[0] = sqrtf(s_red[0] + 1e-12f);
        }
    }
}

// ---------------- launch ---------------------------------------------------
extern "C" void kernel_launch(void* const* d_in, const int* in_sizes, int n_in,
                              void* d_out, int out_size) {
    const float* obj = (const float*)d_in[0];
    const float* sr  = (const float*)d_in[1];
    const float* hv  = (const float*)d_in[2];
    const float* fn  = (const float*)d_in[3];
    const int*   hf  = (const int*)d_in[4];
    float* out = (float*)d_out;

    prep_kernel<<<32, 128>>>(sr, hv, fn, hf);
    nn_kernel<<<512, 256>>>(obj, out);
    hits_kernel<<<NGRP * NFQ, 256>>>(obj, out);
}

// round 10
// speedup vs baseline: 1.4150x; 1.0329x over previous
#include <cuda_runtime.h>

// SR_Loss: NN(obj->sr) + ray-triangle parity interior test + reductions.
// obj 8192x3, sr 4096x3, verts 4100x3, normals 4096x3, faces 4096x3.
// Output: [pen_dist, cmap(8192)] = 8193 f32.
//
// 3 kernels:
//  prep : face constants (28 f/pair, edge-C eliminated by identity) + sr pack
//         + zero hit counters.   128 blocks x 32 thr (latency spread).
//  nn   : balanced NN -> g_D4, cmap.
//  hits : 2048 blocks = 256 point-groups x 8 face-eighths; smem-tiled face
//         records, f32x2 packed sign tests; int atomics for hit counts
//         (deterministic); group-last computes pen partial; global-last
//         reduces to pen_dist.

#define N_OBJ  8192
#define N_SR   4096
#define N_F    4096
#define NPAIR  (N_F / 2)          // 2048
#define EPSF   1e-8f
#define NGRP   (N_OBJ / 32)       // 256 point groups
#define NFQ    8                  // face slices per group
#define PAIRS_PER_FQ (NPAIR / NFQ) // 256

#define TILE_P     128
#define NTILE_FQ   (PAIRS_PER_FQ / TILE_P)   // 2
#define REC_U      7                          // ulonglong2 per pair record
#define TILE_BYTES (TILE_P * REC_U * 16)      // 14336
#define CHUNKS     (TILE_BYTES / 16)          // 896

typedef unsigned long long u64;

// ---------------- scratch (device globals; no allocation allowed) ----------
__device__ float4 g_sr4[N_SR];              // sr point + |s|^2
__device__ float4 g_face4[NPAIR * REC_U];   // pair-interleaved records (28 f/pair)
__device__ float4 g_D4[N_OBJ];              // D = trg - o, .w = |D|^2
__device__ int    g_hits[N_OBJ];            // accumulated hit counts
__device__ float  g_part[NGRP];             // per-group pen partials
__device__ unsigned int g_gctr[NGRP];       // per-group arrival counters
__device__ unsigned int g_ctr;              // global arrival counter

// ---------------- f32x2 packed helpers (sm_103a) ---------------------------
__device__ __forceinline__ u64 pk(float lo, float hi) {
    u64 r;
    asm("mov.b64 %0, {%1, %2};" : "=l"(r)
        : "r"(__float_as_uint(lo)), "r"(__float_as_uint(hi)));
    return r;
}
__device__ __forceinline__ void upku(u64 v, unsigned int& lo, unsigned int& hi) {
    asm("mov.b64 {%0, %1}, %2;" : "=r"(lo), "=r"(hi) : "l"(v));
}
__device__ __forceinline__ u64 f2mul(u64 a, u64 b) {
    u64 r;
    asm("mul.rn.f32x2 %0, %1, %2;" : "=l"(r) : "l"(a), "l"(b));
    return r;
}
__device__ __forceinline__ u64 f2add(u64 a, u64 b) {
    u64 r;
    asm("add.rn.f32x2 %0, %1, %2;" : "=l"(r) : "l"(a), "l"(b));
    return r;
}
__device__ __forceinline__ u64 f2fma(u64 a, u64 b, u64 c) {
    u64 r;
    asm("fma.rn.f32x2 %0, %1, %2, %3;" : "=l"(r) : "l"(a), "l"(b), "l"(c));
    return r;
}
__device__ __forceinline__ void cp16(unsigned int saddr, const void* gaddr) {
    asm volatile("cp.async.cg.shared.global [%0], [%1], 16;"
                 :: "r"(saddr), "l"(gaddr));
}
__device__ __forceinline__ unsigned int smem_u32(const void* p) {
    return (unsigned int)__cvta_generic_to_shared(p);
}

// ---------------- prep -----------------------------------------------------
// Pair record, 14 slots of f32x2 (28 floats, 112B):
//  q0-2: n, q3: v0.n, q4-6: C01, q7: e01, q8-10: C12, q11: e12,
//  q12: E = e01+e12+e20, q13: pad.   (C20 = -(C01+C12) by identity.)
// float index for face f = pair p half h: p*28 + 2q + h.
__global__ void prep_kernel(const float* __restrict__ sr,
                            const float* __restrict__ hv,
                            const float* __restrict__ fn,
                            const int*   __restrict__ hf) {
    int f = blockIdx.x * blockDim.x + threadIdx.x;   // 0..4095
    if (f == 0) g_ctr = 0;
    if (f < NGRP) g_gctr[f] = 0;
    g_hits[f] = 0;
    g_hits[f + N_F] = 0;
    if (f >= N_F) return;

    float sx = sr[3 * f + 0], sy = sr[3 * f + 1], sz = sr[3 * f + 2];
    g_sr4[f] = make_float4(sx, sy, sz, sx * sx + sy * sy + sz * sz);

    int i0 = hf[3 * f + 0], i1 = hf[3 * f + 1], i2 = hf[3 * f + 2];
    float nx = fn[3 * f + 0], ny = fn[3 * f + 1], nz = fn[3 * f + 2];
    float v0x = hv[3 * i0 + 0], v0y = hv[3 * i0 + 1], v0z = hv[3 * i0 + 2];
    float v1x = hv[3 * i1 + 0], v1y = hv[3 * i1 + 1], v1z = hv[3 * i1 + 2];
    float v2x = hv[3 * i2 + 0], v2y = hv[3 * i2 + 1], v2z = hv[3 * i2 + 2];

    float vals[14];
    vals[0] = nx; vals[1] = ny; vals[2] = nz;
    vals[3] = v0x * nx + v0y * ny + v0z * nz;

    float eA, eB, eC;
    {   // edge 01
        float wx = v1x - v0x, wy = v1y - v0y, wz = v1z - v0z;
        float cx = ny * wz - nz * wy, cy = nz * wx - nx * wz, cz = nx * wy - ny * wx;
        vals[4] = cx; vals[5] = cy; vals[6] = cz;
        eA = -(v0x * cx + v0y * cy + v0z * cz);
        vals[7] = eA;
    }
    {   // edge 12
        float wx = v2x - v1x, wy = v2y - v1y, wz = v2z - v1z;
        float cx = ny * wz - nz * wy, cy = nz * wx - nx * wz, cz = nx * wy - ny * wx;
        vals[8] = cx; vals[9] = cy; vals[10] = cz;
        eB = -(v1x * cx + v1y * cy + v1z * cz);
        vals[11] = eB;
    }
    {   // edge 20 (only its offset is needed)
        float wx = v0x - v2x, wy = v0y - v2y, wz = v0z - v2z;
        float cx = ny * wz - nz * wy, cy = nz * wx - nx * wz, cz = nx * wy - ny * wx;
        eC = -(v2x * cx + v2y * cy + v2z * cz);
    }
    vals[12] = eA + eB + eC;
    vals[13] = 0.0f;

    int p = f >> 1, h = f & 1;
    float* out = reinterpret_cast<float*>(g_face4) + p * 28 + h;
#pragma unroll
    for (int q = 0; q < 14; q++) out[2 * q] = vals[q];
}

// ---------------- nn: NN + cmap + D ----------------------------------------
// 512 blocks x 256 thr; 16 points/block, 2 points/warp.
__global__ void __launch_bounds__(256) nn_kernel(const float* __restrict__ obj,
                                                 float* __restrict__ out) {
    int wid = threadIdx.x >> 5, lane = threadIdx.x & 31;
    int pbase = blockIdx.x * 16 + wid * 2;

    float ox0 = obj[3 * (pbase + 0) + 0], oy0 = obj[3 * (pbase + 0) + 1], oz0 = obj[3 * (pbase + 0) + 2];
    float ox1 = obj[3 * (pbase + 1) + 0], oy1 = obj[3 * (pbase + 1) + 1], oz1 = obj[3 * (pbase + 1) + 2];
    float o20 = ox0 * ox0 + oy0 * oy0 + oz0 * oz0;
    float o21 = ox1 * ox1 + oy1 * oy1 + oz1 * oz1;

    float b0 = 3.402823466e38f, b1 = b0;
    int j0 = 0, j1 = 0;

#pragma unroll 4
    for (int j = lane; j < N_SR; j += 32) {
        float4 s = __ldg(&g_sr4[j]);
        float d0 = fmaf(-2.0f, ox0 * s.x + fmaf(oy0, s.y, oz0 * s.z), o20 + s.w);
        float d1 = fmaf(-2.0f, ox1 * s.x + fmaf(oy1, s.y, oz1 * s.z), o21 + s.w);
        if (d0 < b0) { b0 = d0; j0 = j; }
        if (d1 < b1) { b1 = d1; j1 = j; }
    }
#pragma unroll
    for (int off = 16; off; off >>= 1) {
        float t; int tj;
        t = __shfl_down_sync(~0u, b0, off); tj = __shfl_down_sync(~0u, j0, off);
        if (t < b0 || (t == b0 && tj < j0)) { b0 = t; j0 = tj; }
        t = __shfl_down_sync(~0u, b1, off); tj = __shfl_down_sync(~0u, j1, off);
        if (t < b1 || (t == b1 && tj < j1)) { b1 = t; j1 = tj; }
    }

    if (lane == 0) {
        float obx[2] = {ox0, ox1};
        float oby[2] = {oy0, oy1};
        float obz[2] = {oz0, oz1};
        float bb[2] = {b0, b1};
        int   jj[2] = {j0, j1};
#pragma unroll
        for (int k = 0; k < 2; k++) {
            float4 s = g_sr4[jj[k]];
            float Dx = s.x - obx[k], Dy = s.y - oby[k], Dz = s.z - obz[k];
            g_D4[pbase + k] = make_float4(Dx, Dy, Dz, Dx * Dx + Dy * Dy + Dz * Dz);
            float nnd = sqrtf(fmaxf(bb[k], 0.0f));
            out[1 + pbase + k] = 2.0f / (1.0f + expf(100.0f * nnd));
        }
    }
}

// ---------------- hits: parity + reductions --------------------------------
// Block = (group, slice): 32 points (lane=point) x 256 face-pairs.
__global__ void __launch_bounds__(256, 4) hits_kernel(const float* __restrict__ obj,
                                                      float* __restrict__ out) {
    __shared__ __align__(16) char s_face[2][TILE_BYTES];   // 2 x 14 KB
    __shared__ int    s_cnt[8][32];
    __shared__ int    s_glast, s_last;
    __shared__ float  s_red[256];

    int tid = threadIdx.x;
    int wid = tid >> 5, lane = tid & 31;
    int grp = blockIdx.x >> 3, fq = blockIdx.x & 7;
    int pt  = grp * 32 + lane;

    float ox = obj[3 * pt + 0], oy = obj[3 * pt + 1], oz = obj[3 * pt + 2];
    float4 D = __ldg(&g_D4[pt]);

    u64 OX = pk(ox, ox), OY = pk(oy, oy), OZ = pk(oz, oz);
    u64 DX = pk(D.x, D.x), DY = pk(D.y, D.y), DZ = pk(D.z, D.z);
    u64 NEG1 = pk(-1.0f, -1.0f);
    u64 MEPS = pk(-EPSF, -EPSF);
    const unsigned int EPS_BITS = __float_as_uint(EPSF);

    const char* gfb = reinterpret_cast<const char*>(g_face4)
                      + (size_t)fq * PAIRS_PER_FQ * REC_U * 16;

    // stage tile 0
    {
        unsigned int sb = smem_u32(&s_face[0][0]);
#pragma unroll
        for (int k = 0; k < 4; k++) {
            int idx = tid + k * 256;
            if (idx < CHUNKS) cp16(sb + idx * 16, gfb + idx * 16);
        }
        asm volatile("cp.async.commit_group;" ::: "memory");
    }

    int cnt = 0;

    for (int t = 0; t < NTILE_FQ; t++) {
        if (t + 1 < NTILE_FQ) {
            unsigned int sb = smem_u32(&s_face[(t + 1) & 1][0]);
            const char* gsrc = gfb + (t + 1) * TILE_BYTES;
#pragma unroll
            for (int k = 0; k < 4; k++) {
                int idx = tid + k * 256;
                if (idx < CHUNKS) cp16(sb + idx * 16, gsrc + idx * 16);
            }
            asm volatile("cp.async.commit_group;" ::: "memory");
            asm volatile("cp.async.wait_group 1;" ::: "memory");
        } else {
            asm volatile("cp.async.wait_group 0;" ::: "memory");
        }
        __syncthreads();

        const ulonglong2* up = reinterpret_cast<const ulonglong2*>(
            &s_face[t & 1][0]) + (wid * (TILE_P / 8)) * REC_U;

#pragma unroll 4
        for (int lp = 0; lp < TILE_P / 8; lp++, up += REC_U) {
            ulonglong2 t0 = up[0];   // nx | ny
            ulonglong2 t1 = up[1];   // nz | v0n
            ulonglong2 t2 = up[2];   // CAx | CAy
            ulonglong2 t3 = up[3];   // CAz | eA
            ulonglong2 t4 = up[4];   // CBx | CBy
            ulonglong2 t5 = up[5];   // CBz | eB
            u64 Ev = up[6].x;        // E (f32x2)

            // normal block
            u64 no   = f2fma(t0.x, OX, f2fma(t0.y, OY, f2mul(t1.x, OZ)));
            u64 num  = f2fma(no, NEG1, t1.y);      // v0n - n.o
            u64 numn = f2fma(t1.y, NEG1, no);      // n.o - v0n
            u64 den  = f2fma(t0.x, DX, f2fma(t0.y, DY, f2mul(t1.x, DZ)));

            // edge A
            u64 ba = f2fma(t2.x, OX, f2fma(t2.y, OY, f2fma(t3.x, OZ, t3.y)));
            u64 da = f2fma(t2.x, DX, f2fma(t2.y, DY, f2mul(t3.x, DZ)));
            u64 qa = f2fma(ba, den, f2mul(num, da));

            // edge B
            u64 bb_ = f2fma(t4.x, OX, f2fma(t4.y, OY, f2fma(t5.x, OZ, t5.y)));
            u64 db  = f2fma(t4.x, DX, f2fma(t4.y, DY, f2mul(t5.x, DZ)));
            u64 qb  = f2fma(bb_, den, f2mul(num, db));

            // edge C by identity: bc = E - ba - bb, dc = -(da+db)
            u64 sab = f2add(da, db);
            u64 tab = f2add(ba, bb_);
            u64 bc  = f2fma(tab, NEG1, Ev);
            u64 qc  = f2fma(bc, den, f2mul(numn, sab));

            // w = num - EPS*den
            u64 wv = f2fma(MEPS, den, num);

            unsigned int qa0, qa1, qb0, qb1, qc0, qc1, w0, w1, d0, d1;
            upku(qa, qa0, qa1);
            upku(qb, qb0, qb1);
            upku(qc, qc0, qc1);
            upku(wv, w0, w1);
            upku(den, d0, d1);

            unsigned int x0 = ((qa0 ^ d0) | (qb0 ^ d0)) | ((qc0 ^ d0) | (w0 ^ d0));
            unsigned int x1 = ((qa1 ^ d1) | (qb1 ^ d1)) | ((qc1 ^ d1) | (w1 ^ d1));
            cnt += (int)(((int)x0 >= 0) & ((d0 & 0x7fffffffu) > EPS_BITS));
            cnt += (int)(((int)x1 >= 0) & ((d1 & 0x7fffffffu) > EPS_BITS));
        }
        __syncthreads();
    }

    s_cnt[wid][lane] = cnt;
    __syncthreads();

    // warp 0 accumulates this block's per-point counts into gmem (int = exact)
    if (wid == 0) {
        int tot = 0;
#pragma unroll
        for (int k = 0; k < 8; k++) tot += s_cnt[k][lane];
        atomicAdd(&g_hits[pt], tot);
    }

    // group completion
    if (tid == 0) {
        __threadfence();
        unsigned int a = atomicAdd(&g_gctr[grp], 1u);
        s_glast = (a == NFQ - 1) ? 1 : 0;
        s_last = 0;
    }
    __syncthreads();

    if (s_glast) {
        if (wid == 0) {
            int tot;
            asm volatile("ld.global.cg.s32 %0, [%1];" : "=r"(tot)
                         : "l"(&g_hits[pt]));
            float dw;
            asm volatile("ld.global.cg.f32 %0, [%1];" : "=f"(dw)
                         : "l"(reinterpret_cast<const float*>(&g_D4[pt]) + 3));
            float pen = (tot & 1) ? dw : 0.0f;
#pragma unroll
            for (int off = 16; off; off >>= 1)
                pen += __shfl_down_sync(~0u, pen, off);
            if (lane == 0) {
                g_part[grp] = pen;
                __threadfence();
                unsigned int a = atomicAdd(&g_ctr, 1u);
                if (a == NGRP - 1) s_last = 1;
            }
        }
        __syncthreads();

        if (s_last) {
            float v;
            asm volatile("ld.global.cg.f32 %0, [%1];" : "=f"(v)
                         : "l"(&g_part[tid]));
            s_red[tid] = v;
            __syncthreads();
#pragma unroll
            for (int off = 128; off; off >>= 1) {
                if (tid < off) s_red[tid] += s_red[tid + off];
                __syncthreads();
            }
            if (tid == 0) out[0] = sqrtf(s_red[0] + 1e-12f);
        }
    }
}

// ---------------- launch ---------------------------------------------------
extern "C" void kernel_launch(void* const* d_in, const int* in_sizes, int n_in,
                              void* d_out, int out_size) {
    const float* obj = (const float*)d_in[0];
    const float* sr  = (const float*)d_in[1];
    const float* hv  = (const float*)d_in[2];
    const float* fn  = (const float*)d_in[3];
    const int*   hf  = (const int*)d_in[4];
    float* out = (float*)d_out;

    prep_kernel<<<128, 32>>>(sr, hv, fn, hf);
    nn_kernel<<<512, 256>>>(obj, out);
    hits_kernel<<<NGRP * NFQ, 256>>>(obj, out);
}

// round 11
// speedup vs baseline: 1.4164x; 1.0009x over previous
#include <cuda_runtime.h>

// SR_Loss: NN(obj->sr) + ray-triangle parity interior test + reductions.
// obj 8192x3, sr 4096x3, verts 4100x3, normals 4096x3, faces 4096x3.
// Output: [pen_dist, cmap(8192)] = 8193 f32.
//
// 2 kernels:
//  prep_nn : blocks 0-15 build face constants (28 f/pair, edge-C eliminated)
//            + zero counters; blocks 16-527 do NN -> g_D4 + cmap (reads raw sr,
//            no dependency on the prep blocks).
//  hits    : 2048 blocks = 256 point-groups x 8 face-slices; smem-tiled face
//            records, f32x2 packed sign tests; int atomics for hit counts;
//            group-last computes pen partial; global-last reduces pen_dist.

#define N_OBJ  8192
#define N_SR   4096
#define N_F    4096
#define NPAIR  (N_F / 2)          // 2048
#define EPSF   1e-8f
#define NGRP   (N_OBJ / 32)       // 256 point groups
#define NFQ    8                  // face slices per group
#define PAIRS_PER_FQ (NPAIR / NFQ) // 256

#define TILE_P     128
#define NTILE_FQ   (PAIRS_PER_FQ / TILE_P)   // 2
#define REC_U      7                          // ulonglong2 per pair record
#define TILE_BYTES (TILE_P * REC_U * 16)      // 14336
#define CHUNKS     (TILE_BYTES / 16)          // 896

#define PREP_BLKS  16
#define NN_BLKS    512

typedef unsigned long long u64;

// ---------------- scratch (device globals; no allocation allowed) ----------
__device__ float4 g_face4[NPAIR * REC_U];   // pair-interleaved records (28 f/pair)
__device__ float4 g_D4[N_OBJ];              // D = trg - o, .w = |D|^2
__device__ int    g_hits[N_OBJ];            // accumulated hit counts
__device__ float  g_part[NGRP];             // per-group pen partials
__device__ unsigned int g_gctr[NGRP];       // per-group arrival counters
__device__ unsigned int g_ctr;              // global arrival counter

// ---------------- f32x2 packed helpers (sm_103a) ---------------------------
__device__ __forceinline__ u64 pk(float lo, float hi) {
    u64 r;
    asm("mov.b64 %0, {%1, %2};" : "=l"(r)
        : "r"(__float_as_uint(lo)), "r"(__float_as_uint(hi)));
    return r;
}
__device__ __forceinline__ void upku(u64 v, unsigned int& lo, unsigned int& hi) {
    asm("mov.b64 {%0, %1}, %2;" : "=r"(lo), "=r"(hi) : "l"(v));
}
__device__ __forceinline__ u64 f2mul(u64 a, u64 b) {
    u64 r;
    asm("mul.rn.f32x2 %0, %1, %2;" : "=l"(r) : "l"(a), "l"(b));
    return r;
}
__device__ __forceinline__ u64 f2add(u64 a, u64 b) {
    u64 r;
    asm("add.rn.f32x2 %0, %1, %2;" : "=l"(r) : "l"(a), "l"(b));
    return r;
}
__device__ __forceinline__ u64 f2fma(u64 a, u64 b, u64 c) {
    u64 r;
    asm("fma.rn.f32x2 %0, %1, %2, %3;" : "=l"(r) : "l"(a), "l"(b), "l"(c));
    return r;
}
__device__ __forceinline__ void cp16(unsigned int saddr, const void* gaddr) {
    asm volatile("cp.async.cg.shared.global [%0], [%1], 16;"
                 :: "r"(saddr), "l"(gaddr));
}
__device__ __forceinline__ unsigned int smem_u32(const void* p) {
    return (unsigned int)__cvta_generic_to_shared(p);
}

// ---------------- prep_nn --------------------------------------------------
// Pair record, 14 slots of f32x2 (28 floats, 112B):
//  q0-2: n, q3: v0.n, q4-6: C01, q7: e01, q8-10: C12, q11: e12,
//  q12: E = e01+e12+e20, q13: pad.   (C20 = -(C01+C12) by identity.)
// float index for face f = pair p half h: p*28 + 2q + h.
__global__ void __launch_bounds__(256) prep_nn_kernel(const float* __restrict__ sr,
                                                      const float* __restrict__ hv,
                                                      const float* __restrict__ fn,
                                                      const int*   __restrict__ hf,
                                                      const float* __restrict__ obj,
                                                      float* __restrict__ out) {
    if (blockIdx.x < PREP_BLKS) {
        // ---------------- prep part ----------------
        int f = blockIdx.x * 256 + threadIdx.x;   // 0..4095
        if (f == 0) g_ctr = 0;
        if (f < NGRP) g_gctr[f] = 0;
        g_hits[f] = 0;
        g_hits[f + N_F] = 0;

        int i0 = hf[3 * f + 0], i1 = hf[3 * f + 1], i2 = hf[3 * f + 2];
        float nx = fn[3 * f + 0], ny = fn[3 * f + 1], nz = fn[3 * f + 2];
        float v0x = hv[3 * i0 + 0], v0y = hv[3 * i0 + 1], v0z = hv[3 * i0 + 2];
        float v1x = hv[3 * i1 + 0], v1y = hv[3 * i1 + 1], v1z = hv[3 * i1 + 2];
        float v2x = hv[3 * i2 + 0], v2y = hv[3 * i2 + 1], v2z = hv[3 * i2 + 2];

        float vals[14];
        vals[0] = nx; vals[1] = ny; vals[2] = nz;
        vals[3] = v0x * nx + v0y * ny + v0z * nz;

        float eA, eB, eC;
        {   // edge 01
            float wx = v1x - v0x, wy = v1y - v0y, wz = v1z - v0z;
            float cx = ny * wz - nz * wy, cy = nz * wx - nx * wz, cz = nx * wy - ny * wx;
            vals[4] = cx; vals[5] = cy; vals[6] = cz;
            eA = -(v0x * cx + v0y * cy + v0z * cz);
            vals[7] = eA;
        }
        {   // edge 12
            float wx = v2x - v1x, wy = v2y - v1y, wz = v2z - v1z;
            float cx = ny * wz - nz * wy, cy = nz * wx - nx * wz, cz = nx * wy - ny * wx;
            vals[8] = cx; vals[9] = cy; vals[10] = cz;
            eB = -(v1x * cx + v1y * cy + v1z * cz);
            vals[11] = eB;
        }
        {   // edge 20 (only its offset is needed)
            float wx = v0x - v2x, wy = v0y - v2y, wz = v0z - v2z;
            float cx = ny * wz - nz * wy, cy = nz * wx - nx * wz, cz = nx * wy - ny * wx;
            eC = -(v2x * cx + v2y * cy + v2z * cz);
        }
        vals[12] = eA + eB + eC;
        vals[13] = 0.0f;

        int p = f >> 1, h = f & 1;
        float* o = reinterpret_cast<float*>(g_face4) + p * 28 + h;
#pragma unroll
        for (int q = 0; q < 14; q++) o[2 * q] = vals[q];
        return;
    }

    // ---------------- nn part (self-sufficient: reads raw sr) --------------
    int wid = threadIdx.x >> 5, lane = threadIdx.x & 31;
    int pbase = (blockIdx.x - PREP_BLKS) * 16 + wid * 2;

    float ox0 = obj[3 * (pbase + 0) + 0], oy0 = obj[3 * (pbase + 0) + 1], oz0 = obj[3 * (pbase + 0) + 2];
    float ox1 = obj[3 * (pbase + 1) + 0], oy1 = obj[3 * (pbase + 1) + 1], oz1 = obj[3 * (pbase + 1) + 2];
    float o20 = ox0 * ox0 + oy0 * oy0 + oz0 * oz0;
    float o21 = ox1 * ox1 + oy1 * oy1 + oz1 * oz1;

    float b0 = 3.402823466e38f, b1 = b0;
    int j0 = 0, j1 = 0;

#pragma unroll 4
    for (int j = lane; j < N_SR; j += 32) {
        float sx = __ldg(&sr[3 * j + 0]);
        float sy = __ldg(&sr[3 * j + 1]);
        float sz = __ldg(&sr[3 * j + 2]);
        float s2 = sx * sx + sy * sy + sz * sz;
        float d0 = fmaf(-2.0f, ox0 * sx + fmaf(oy0, sy, oz0 * sz), o20 + s2);
        float d1 = fmaf(-2.0f, ox1 * sx + fmaf(oy1, sy, oz1 * sz), o21 + s2);
        if (d0 < b0) { b0 = d0; j0 = j; }
        if (d1 < b1) { b1 = d1; j1 = j; }
    }
#pragma unroll
    for (int off = 16; off; off >>= 1) {
        float t; int tj;
        t = __shfl_down_sync(~0u, b0, off); tj = __shfl_down_sync(~0u, j0, off);
        if (t < b0 || (t == b0 && tj < j0)) { b0 = t; j0 = tj; }
        t = __shfl_down_sync(~0u, b1, off); tj = __shfl_down_sync(~0u, j1, off);
        if (t < b1 || (t == b1 && tj < j1)) { b1 = t; j1 = tj; }
    }

    if (lane == 0) {
        float obx[2] = {ox0, ox1};
        float oby[2] = {oy0, oy1};
        float obz[2] = {oz0, oz1};
        float bb[2] = {b0, b1};
        int   jj[2] = {j0, j1};
#pragma unroll
        for (int k = 0; k < 2; k++) {
            float sx = sr[3 * jj[k] + 0], sy = sr[3 * jj[k] + 1], sz = sr[3 * jj[k] + 2];
            float Dx = sx - obx[k], Dy = sy - oby[k], Dz = sz - obz[k];
            g_D4[pbase + k] = make_float4(Dx, Dy, Dz, Dx * Dx + Dy * Dy + Dz * Dz);
            float nnd = sqrtf(fmaxf(bb[k], 0.0f));
            out[1 + pbase + k] = 2.0f / (1.0f + expf(100.0f * nnd));
        }
    }
}

// ---------------- hits: parity + reductions --------------------------------
// Block = (group, slice): 32 points (lane=point) x 256 face-pairs.
__global__ void __launch_bounds__(256, 4) hits_kernel(const float* __restrict__ obj,
                                                      float* __restrict__ out) {
    __shared__ __align__(16) char s_face[2][TILE_BYTES];   // 2 x 14 KB
    __shared__ int    s_cnt[8][32];
    __shared__ int    s_glast, s_last;
    __shared__ float  s_red[256];

    int tid = threadIdx.x;
    int wid = tid >> 5, lane = tid & 31;
    int grp = blockIdx.x >> 3, fq = blockIdx.x & 7;
    int pt  = grp * 32 + lane;

    float ox = obj[3 * pt + 0], oy = obj[3 * pt + 1], oz = obj[3 * pt + 2];
    float4 D = __ldg(&g_D4[pt]);

    u64 OX = pk(ox, ox), OY = pk(oy, oy), OZ = pk(oz, oz);
    u64 DX = pk(D.x, D.x), DY = pk(D.y, D.y), DZ = pk(D.z, D.z);
    u64 NEG1 = pk(-1.0f, -1.0f);
    u64 MEPS = pk(-EPSF, -EPSF);
    const unsigned int EPS_BITS = __float_as_uint(EPSF);
    const unsigned int SGN = 0x80000000u;

    const char* gfb = reinterpret_cast<const char*>(g_face4)
                      + (size_t)fq * PAIRS_PER_FQ * REC_U * 16;

    // stage tile 0
    {
        unsigned int sb = smem_u32(&s_face[0][0]);
#pragma unroll
        for (int k = 0; k < 4; k++) {
            int idx = tid + k * 256;
            if (idx < CHUNKS) cp16(sb + idx * 16, gfb + idx * 16);
        }
        asm volatile("cp.async.commit_group;" ::: "memory");
    }

    int cnt = 0;

    for (int t = 0; t < NTILE_FQ; t++) {
        if (t + 1 < NTILE_FQ) {
            unsigned int sb = smem_u32(&s_face[(t + 1) & 1][0]);
            const char* gsrc = gfb + (t + 1) * TILE_BYTES;
#pragma unroll
            for (int k = 0; k < 4; k++) {
                int idx = tid + k * 256;
                if (idx < CHUNKS) cp16(sb + idx * 16, gsrc + idx * 16);
            }
            asm volatile("cp.async.commit_group;" ::: "memory");
            asm volatile("cp.async.wait_group 1;" ::: "memory");
        } else {
            asm volatile("cp.async.wait_group 0;" ::: "memory");
        }
        __syncthreads();

        const ulonglong2* up = reinterpret_cast<const ulonglong2*>(
            &s_face[t & 1][0]) + (wid * (TILE_P / 8)) * REC_U;

#pragma unroll 4
        for (int lp = 0; lp < TILE_P / 8; lp++, up += REC_U) {
            ulonglong2 t0 = up[0];   // nx | ny
            ulonglong2 t1 = up[1];   // nz | v0n
            ulonglong2 t2 = up[2];   // CAx | CAy
            ulonglong2 t3 = up[3];   // CAz | eA
            ulonglong2 t4 = up[4];   // CBx | CBy
            ulonglong2 t5 = up[5];   // CBz | eB
            u64 Ev = up[6].x;        // E (f32x2)

            // normal block
            u64 no   = f2fma(t0.x, OX, f2fma(t0.y, OY, f2mul(t1.x, OZ)));
            u64 num  = f2fma(no, NEG1, t1.y);      // v0n - n.o
            u64 den  = f2fma(t0.x, DX, f2fma(t0.y, DY, f2mul(t1.x, DZ)));

            // edge A
            u64 ba = f2fma(t2.x, OX, f2fma(t2.y, OY, f2fma(t3.x, OZ, t3.y)));
            u64 da = f2fma(t2.x, DX, f2fma(t2.y, DY, f2mul(t3.x, DZ)));
            u64 qa = f2fma(ba, den, f2mul(num, da));

            // edge B
            u64 bb_ = f2fma(t4.x, OX, f2fma(t4.y, OY, f2fma(t5.x, OZ, t5.y)));
            u64 db  = f2fma(t4.x, DX, f2fma(t4.y, DY, f2mul(t5.x, DZ)));
            u64 qb  = f2fma(bb_, den, f2mul(num, db));

            // edge C (negated) by identity: C20 = -(C01+C12), e-sum E.
            //   qc  = (E - ba - bb)*den - num*(da+db)
            //   qcn = -qc = (ba + bb - E)*den + num*(da+db)
            // sign(qc)==sign(den)  <=>  sign(qcn)==sign(-den)
            u64 sab = f2add(da, db);
            u64 tab = f2add(ba, bb_);
            u64 nbc = f2fma(Ev, NEG1, tab);               // tab - E
            u64 qcn = f2fma(nbc, den, f2mul(num, sab));

            // w = num - EPS*den
            u64 wv = f2fma(MEPS, den, num);

            unsigned int qa0, qa1, qb0, qb1, qc0, qc1, w0, w1, d0, d1;
            upku(qa, qa0, qa1);
            upku(qb, qb0, qb1);
            upku(qcn, qc0, qc1);
            upku(wv, w0, w1);
            upku(den, d0, d1);

            unsigned int dn0 = d0 ^ SGN, dn1 = d1 ^ SGN;
            unsigned int x0 = ((qa0 ^ d0) | (qb0 ^ d0)) | ((qc0 ^ dn0) | (w0 ^ d0));
            unsigned int x1 = ((qa1 ^ d1) | (qb1 ^ d1)) | ((qc1 ^ dn1) | (w1 ^ d1));
            cnt += (int)(((int)x0 >= 0) & ((d0 & 0x7fffffffu) > EPS_BITS));
            cnt += (int)(((int)x1 >= 0) & ((d1 & 0x7fffffffu) > EPS_BITS));
        }
        __syncthreads();
    }

    s_cnt[wid][lane] = cnt;
    __syncthreads();

    // warp 0 accumulates this block's per-point counts into gmem (int = exact)
    if (wid == 0) {
        int tot = 0;
#pragma unroll
        for (int k = 0; k < 8; k++) tot += s_cnt[k][lane];
        atomicAdd(&g_hits[pt], tot);
    }

    // group completion
    if (tid == 0) {
        __threadfence();
        unsigned int a = atomicAdd(&g_gctr[grp], 1u);
        s_glast = (a == NFQ - 1) ? 1 : 0;
        s_last = 0;
    }
    __syncthreads();

    if (s_glast) {
        if (wid == 0) {
            int tot;
            asm volatile("ld.global.cg.s32 %0, [%1];" : "=r"(tot)
                         : "l"(&g_hits[pt]));
            float dw;
            asm volatile("ld.global.cg.f32 %0, [%1];" : "=f"(dw)
                         : "l"(reinterpret_cast<const float*>(&g_D4[pt]) + 3));
            float pen = (tot & 1) ? dw : 0.0f;
#pragma unroll
            for (int off = 16; off; off >>= 1)
                pen += __shfl_down_sync(~0u, pen, off);
            if (lane == 0) {
                g_part[grp] = pen;
                __threadfence();
                unsigned int a = atomicAdd(&g_ctr, 1u);
                if (a == NGRP - 1) s_last = 1;
            }
        }
        __syncthreads();

        if (s_last) {
            float v;
            asm volatile("ld.global.cg.f32 %0, [%1];" : "=f"(v)
                         : "l"(&g_part[tid]));
            s_red[tid] = v;
            __syncthreads();
#pragma unroll
            for (int off = 128; off; off >>= 1) {
                if (tid < off) s_red[tid] += s_red[tid + off];
                __syncthreads();
            }
            if (tid == 0) out[0] = sqrtf(s_red[0] + 1e-12f);
        }
    }
}

// ---------------- launch ---------------------------------------------------
extern "C" void kernel_launch(void* const* d_in, const int* in_sizes, int n_in,
                              void* d_out, int out_size) {
    const float* obj = (const float*)d_in[0];
    const float* sr  = (const float*)d_in[1];
    const float* hv  = (const float*)d_in[2];
    const float* fn  = (const float*)d_in[3];
    const int*   hf  = (const int*)d_in[4];
    float* out = (float*)d_out;

    prep_nn_kernel<<<PREP_BLKS + NN_BLKS, 256>>>(sr, hv, fn, hf, obj, out);
    hits_kernel<<<NGRP * NFQ, 256>>>(obj, out);
}